// round 10
// baseline (speedup 1.0000x reference)
#include <cuda_runtime.h>
#include <cuda_bf16.h>
#include <math.h>

#define NN 4096
#define KN 48
#define CC 128
#define EC 384
#define HD 512

// ---------------- scratch (device globals: allocation-free) ----------------
__device__ float g_node_pre[NN * CC];   // node @ W1a^T + b_m1
__device__ float g_S[NN * CC];          // sum_k attn * h2
__device__ float g_A[NN];               // sum_k attn
__device__ float g_X[NN * CC];          // post-LN1 x
__device__ float g_H[NN * HD];          // gelu(x @ Wd1^T + bd1)
__device__ unsigned g_Wp1T[128 * 192];  // W1b packed bf16x2, n-major: [c][kk]
__device__ unsigned g_Wp2T[128 * 64];   // W2  packed bf16x2, n-major: [c][kk]

__device__ __forceinline__ float gelu_f(float x) {
    return 0.5f * x * (1.0f + erff(x * 0.70710678118654752440f));
}

__device__ __forceinline__ unsigned pk(float a, float b) {
    __nv_bfloat162 t = __floats2bfloat162_rn(a, b);
    return *(unsigned*)&t;
}

__device__ __forceinline__ void mma_bf16(float c[4], const unsigned a[4], const unsigned b[2]) {
    asm volatile(
        "mma.sync.aligned.m16n8k16.row.col.f32.bf16.bf16.f32 "
        "{%0,%1,%2,%3},{%4,%5,%6,%7},{%8,%9},{%0,%1,%2,%3};\n"
        : "+f"(c[0]), "+f"(c[1]), "+f"(c[2]), "+f"(c[3])
        : "r"(a[0]), "r"(a[1]), "r"(a[2]), "r"(a[3]), "r"(b[0]), "r"(b[1]));
}

__device__ __forceinline__ void ldsm4(unsigned r[4], unsigned addr) {
    asm volatile("ldmatrix.sync.aligned.m8n8.x4.shared.b16 {%0,%1,%2,%3}, [%4];"
                 : "=r"(r[0]), "=r"(r[1]), "=r"(r[2]), "=r"(r[3]) : "r"(addr));
}

#define CP_ASYNC16(dst, src) \
    asm volatile("cp.async.cg.shared.global [%0], [%1], 16;" :: "r"(dst), "l"(src))
#define CP_COMMIT() asm volatile("cp.async.commit_group;" ::)
#define CP_WAIT0()  asm volatile("cp.async.wait_group 0;" ::)

// =================== Kprep: pack weights to bf16x2 (n-major) ===============
__global__ __launch_bounds__(256)
void k_prep(const float* __restrict__ W1, const float* __restrict__ W2) {
    int idx = blockIdx.x * 256 + threadIdx.x;
    if (idx < 128 * 192) {
        int c = idx / 192, kk = idx % 192;
        g_Wp1T[idx] = pk(W1[(size_t)c * 512 + 128 + 2 * kk],
                         W1[(size_t)c * 512 + 128 + 2 * kk + 1]);
    } else if (idx < 128 * 192 + 128 * 64) {
        int j = idx - 128 * 192;
        int c = j >> 6, kk = j & 63;
        g_Wp2T[j] = pk(W2[(size_t)c * 128 + 2 * kk],
                       W2[(size_t)c * 128 + 2 * kk + 1]);
    }
}

// ======================= K0: node_pre = node @ W1a^T + b1 ==================
__global__ __launch_bounds__(256)
void k0_node_pre(const float* __restrict__ node, const float* __restrict__ W1,
                 const float* __restrict__ b1) {
    extern __shared__ float sm[];
    float* sX = sm;           // 32*128
    float* sW = sm + 4096;    // 128*128  sW[k][c] = W1[c*512 + k]
    const int tid = threadIdx.x, tx = tid & 15, ty = tid >> 4;
    const int n0 = blockIdx.x * 32;

#pragma unroll
    for (int m = 0; m < 4; ++m) {
        int f4 = tid + 256 * m;
        int r = f4 >> 5, c4 = f4 & 31;
        *(float4*)(sX + r * 128 + c4 * 4) =
            *(const float4*)(node + (size_t)(n0 + r) * 128 + c4 * 4);
    }
#pragma unroll
    for (int m = 0; m < 16; ++m) {
        int idx = tid + 256 * m;
        int c = idx & 127, k4 = idx >> 7;
        float4 v = *(const float4*)(W1 + (size_t)c * 512 + k4 * 4);
        sW[(k4 * 4 + 0) * 128 + c] = v.x;
        sW[(k4 * 4 + 1) * 128 + c] = v.y;
        sW[(k4 * 4 + 2) * 128 + c] = v.z;
        sW[(k4 * 4 + 3) * 128 + c] = v.w;
    }
    __syncthreads();

    float acc[2][8] = {};
#pragma unroll
    for (int kk = 0; kk < 128; kk += 4) {
        float a[2][4];
#pragma unroll
        for (int i = 0; i < 2; ++i) {
            float4 t = *(float4*)(sX + (ty + 16 * i) * 128 + kk);
            a[i][0] = t.x; a[i][1] = t.y; a[i][2] = t.z; a[i][3] = t.w;
        }
#pragma unroll
        for (int q = 0; q < 4; ++q) {
            float4 b0 = *(float4*)(sW + (kk + q) * 128 + tx * 8);
            float4 b1v = *(float4*)(sW + (kk + q) * 128 + tx * 8 + 4);
            float bb[8] = {b0.x, b0.y, b0.z, b0.w, b1v.x, b1v.y, b1v.z, b1v.w};
#pragma unroll
            for (int i = 0; i < 2; ++i)
#pragma unroll
                for (int j = 0; j < 8; ++j) acc[i][j] += a[i][q] * bb[j];
        }
    }
#pragma unroll
    for (int i = 0; i < 2; ++i) {
        int r = n0 + ty + 16 * i;
#pragma unroll
        for (int j = 0; j < 8; ++j) {
            int c = tx * 8 + j;
            g_node_pre[(size_t)r * 128 + c] = acc[i][j] + b1[c];
        }
    }
}

// ================ K1: per-node-pair edge message kernel (bf16 MMA) =========
// 2 nodes/block, 8 warps = mg(2) x ng(4). ldmatrix fragments, double-buffered
// k-tiles (register-staged A + cp.async B).
#define W_SA0 0
#define W_SA1 3456
#define W_SB0 6912
#define W_SB1 11520
#define W_SH  0
#define W_SW2 6912
#define W_NP  16128
#define W_AT  16384
#define W_B2  16512
#define S1_WORDS 16640

__global__ __launch_bounds__(256, 2)
void k1_edges(const float* __restrict__ edge, const float* __restrict__ attn,
              const float* __restrict__ b2) {
    extern __shared__ unsigned smu[];
    float* sNP = (float*)(smu + W_NP);
    float* sAt = (float*)(smu + W_AT);
    float* sb2 = (float*)(smu + W_B2);

    const int tid = threadIdx.x;
    const int lane = tid & 31, wid = tid >> 5;
    const int mg = wid >> 2;
    const int ng = wid & 3;
    const int g = lane >> 2, q = lane & 3;
    const int n0 = blockIdx.x * 2;
    const float* eb = edge + (size_t)n0 * (KN * EC);
    const unsigned smem_base = (unsigned)__cvta_generic_to_shared(smu);

    sNP[tid] = g_node_pre[(size_t)n0 * 128 + tid];
    if (tid < 96) sAt[tid] = attn[(size_t)n0 * KN + tid];
    if (tid < 128) sb2[tid] = b2[tid];

    // ---- prologue: tile 0 into buf0 ----
#pragma unroll
    for (int m = 0; m < 6; ++m) {
        int f = tid + 256 * m;
        int row = f >> 4, c4 = f & 15;
        float4 v = *(const float4*)(eb + (size_t)row * EC + c4 * 4);
        *(uint2*)(smu + W_SA0 + row * 36 + c4 * 2) =
            make_uint2(pk(v.x, v.y), pk(v.z, v.w));
    }
#pragma unroll
    for (int m = 0; m < 4; ++m) {
        int f = tid + 256 * m;
        int row = f >> 3, j = f & 7;
        CP_ASYNC16(smem_base + (W_SB0 + row * 36 + j * 4) * 4,
                   g_Wp1T + (size_t)row * 192 + j * 4);
    }
    CP_COMMIT();
    CP_WAIT0();
    __syncthreads();

    // ---- fragment base addresses (bytes) ----
    const unsigned aB = smem_base + (mg * 48 + (lane & 15)) * 144 + (lane >> 4) * 16;
    const unsigned bB = smem_base + W_SB0 * 4 +
                        (ng * 32 + (lane & 7) + (lane >> 4) * 8) * 144 +
                        ((lane >> 3) & 1) * 16;

    float acc[3][4][4] = {};
    float4 st[6];

    // ---------------- GEMM1b over edge context: 6 k-tiles of 64 ------------
    for (int kt = 0; kt < 6; ++kt) {
        if (kt < 5) {
#pragma unroll
            for (int m = 0; m < 6; ++m) {
                int f = tid + 256 * m;
                int row = f >> 4, c4 = f & 15;
                st[m] = *(const float4*)(eb + (size_t)row * EC + (kt + 1) * 64 + c4 * 4);
            }
            unsigned dstB = smem_base + (((kt + 1) & 1) ? W_SB1 : W_SB0) * 4;
#pragma unroll
            for (int m = 0; m < 4; ++m) {
                int f = tid + 256 * m;
                int row = f >> 3, j = f & 7;
                CP_ASYNC16(dstB + row * 144 + j * 16,
                           g_Wp1T + (size_t)row * 192 + (kt + 1) * 32 + j * 4);
            }
            CP_COMMIT();
        }
        const unsigned aO = aB + (kt & 1) * 13824;
        const unsigned bO = bB + (kt & 1) * 18432;
#pragma unroll
        for (int s = 0; s < 4; ++s) {
            unsigned a0[4], a1[4], a2[4], bx[4], by[4];
            ldsm4(a0, aO + s * 32);
            ldsm4(a1, aO + 2304 + s * 32);
            ldsm4(a2, aO + 4608 + s * 32);
            ldsm4(bx, bO + s * 32);
            ldsm4(by, bO + 2304 + s * 32);
            mma_bf16(acc[0][0], a0, &bx[0]); mma_bf16(acc[0][1], a0, &bx[2]);
            mma_bf16(acc[0][2], a0, &by[0]); mma_bf16(acc[0][3], a0, &by[2]);
            mma_bf16(acc[1][0], a1, &bx[0]); mma_bf16(acc[1][1], a1, &bx[2]);
            mma_bf16(acc[1][2], a1, &by[0]); mma_bf16(acc[1][3], a1, &by[2]);
            mma_bf16(acc[2][0], a2, &bx[0]); mma_bf16(acc[2][1], a2, &bx[2]);
            mma_bf16(acc[2][2], a2, &by[0]); mma_bf16(acc[2][3], a2, &by[2]);
        }
        if (kt < 5) {
            unsigned* dA = smu + (((kt + 1) & 1) ? W_SA1 : W_SA0);
#pragma unroll
            for (int m = 0; m < 6; ++m) {
                int f = tid + 256 * m;
                int row = f >> 4, c4 = f & 15;
                *(uint2*)(dA + row * 36 + c4 * 2) =
                    make_uint2(pk(st[m].x, st[m].y), pk(st[m].z, st[m].w));
            }
            CP_WAIT0();
        }
        __syncthreads();
    }

    // ---- epilogue 1: h1 = gelu(node_pre + acc) -> sH; kick W2 copy --------
#pragma unroll
    for (int mi = 0; mi < 3; ++mi) {
        int r0 = mg * 48 + mi * 16 + g;
#pragma unroll
        for (int t = 0; t < 4; ++t) {
            int c = ng * 32 + t * 8 + 2 * q;
            float np0 = sNP[mg * 128 + c], np1 = sNP[mg * 128 + c + 1];
            unsigned lo = pk(gelu_f(acc[mi][t][0] + np0), gelu_f(acc[mi][t][1] + np1));
            unsigned hi = pk(gelu_f(acc[mi][t][2] + np0), gelu_f(acc[mi][t][3] + np1));
            smu[W_SH + r0 * 68 + ng * 16 + t * 4 + q] = lo;
            smu[W_SH + (r0 + 8) * 68 + ng * 16 + t * 4 + q] = hi;
            acc[mi][t][0] = acc[mi][t][1] = acc[mi][t][2] = acc[mi][t][3] = 0.f;
        }
    }
#pragma unroll
    for (int m = 0; m < 8; ++m) {
        int f = tid + 256 * m;
        int row = f >> 4, j = f & 15;
        CP_ASYNC16(smem_base + (W_SW2 + row * 68 + j * 4) * 4,
                   g_Wp2T + (size_t)row * 64 + j * 4);
    }
    CP_COMMIT();
    if (tid < 2) {
        float s = 0.f;
#pragma unroll
        for (int k = 0; k < KN; ++k) s += sAt[tid * KN + k];
        g_A[n0 + tid] = s;
    }
    CP_WAIT0();
    __syncthreads();

    // ---------------- GEMM2: h1 @ W2^T (8 k16 steps) -----------------------
    const unsigned a2B = smem_base + W_SH * 4 +
                         (mg * 48 + (lane & 15)) * 272 + (lane >> 4) * 16;
    const unsigned b2B = smem_base + W_SW2 * 4 +
                         (ng * 32 + (lane & 7) + (lane >> 4) * 8) * 272 +
                         ((lane >> 3) & 1) * 16;
#pragma unroll
    for (int s = 0; s < 8; ++s) {
        unsigned a0[4], a1[4], a2[4], bx[4], by[4];
        ldsm4(a0, a2B + s * 32);
        ldsm4(a1, a2B + 4352 + s * 32);
        ldsm4(a2, a2B + 8704 + s * 32);
        ldsm4(bx, b2B + s * 32);
        ldsm4(by, b2B + 4352 + s * 32);
        mma_bf16(acc[0][0], a0, &bx[0]); mma_bf16(acc[0][1], a0, &bx[2]);
        mma_bf16(acc[0][2], a0, &by[0]); mma_bf16(acc[0][3], a0, &by[2]);
        mma_bf16(acc[1][0], a1, &bx[0]); mma_bf16(acc[1][1], a1, &bx[2]);
        mma_bf16(acc[1][2], a1, &by[0]); mma_bf16(acc[1][3], a1, &by[2]);
        mma_bf16(acc[2][0], a2, &bx[0]); mma_bf16(acc[2][1], a2, &bx[2]);
        mma_bf16(acc[2][2], a2, &by[0]); mma_bf16(acc[2][3], a2, &by[2]);
    }

    // ---- epilogue 2: gelu(+b2), attn-weighted reduce over the 48 rows -----
#pragma unroll
    for (int t = 0; t < 4; ++t) {
        int c = ng * 32 + t * 8 + 2 * q;
        float bc0 = sb2[c], bc1 = sb2[c + 1];
        float p0 = 0.f, p1 = 0.f;
#pragma unroll
        for (int mi = 0; mi < 3; ++mi) {
            int r0 = mi * 16 + g;
            float w0 = sAt[mg * 48 + r0];
            float w1 = sAt[mg * 48 + r0 + 8];
            p0 += w0 * gelu_f(acc[mi][t][0] + bc0) + w1 * gelu_f(acc[mi][t][2] + bc0);
            p1 += w0 * gelu_f(acc[mi][t][1] + bc1) + w1 * gelu_f(acc[mi][t][3] + bc1);
        }
#pragma unroll
        for (int off = 16; off >= 4; off >>= 1) {
            p0 += __shfl_xor_sync(0xffffffffu, p0, off);
            p1 += __shfl_xor_sync(0xffffffffu, p1, off);
        }
        if (lane < 4) {
            int cc = ng * 32 + t * 8 + 2 * lane;
            g_S[(size_t)(n0 + mg) * 128 + cc] = p0;
            g_S[(size_t)(n0 + mg) * 128 + cc + 1] = p1;
        }
    }
}

// ========= K2: x = LN1(node + (W3 @ S + A*b3)/30) -> g_X (fused) ===========
__global__ __launch_bounds__(256)
void k2_ln1(const float* __restrict__ node, const float* __restrict__ W3,
            const float* __restrict__ b3, const float* __restrict__ g1,
            const float* __restrict__ be1) {
    extern __shared__ float sm[];
    float* sS = sm;            // 32*128
    float* sW = sm + 4096;     // 128*128  sW[c][d] = W3[d*128 + c]
    float* sRs = sm + 20480;   // 512
    float* sRq = sm + 20992;   // 512
    const int tid = threadIdx.x, tx = tid & 15, ty = tid >> 4;
    const int n0 = blockIdx.x * 32;

#pragma unroll
    for (int m = 0; m < 4; ++m) {
        int f4 = tid + 256 * m;
        int r = f4 >> 5, c4 = f4 & 31;
        *(float4*)(sS + r * 128 + c4 * 4) =
            *(const float4*)(g_S + (size_t)(n0 + r) * 128 + c4 * 4);
    }
#pragma unroll
    for (int m = 0; m < 16; ++m) {
        int idx = tid + 256 * m;
        int d = idx & 127, c4 = idx >> 7;
        float4 v = *(const float4*)(W3 + (size_t)d * 128 + c4 * 4);
        sW[(c4 * 4 + 0) * 128 + d] = v.x;
        sW[(c4 * 4 + 1) * 128 + d] = v.y;
        sW[(c4 * 4 + 2) * 128 + d] = v.z;
        sW[(c4 * 4 + 3) * 128 + d] = v.w;
    }
    __syncthreads();

    float acc[2][8] = {};
#pragma unroll
    for (int kk = 0; kk < 128; kk += 4) {
        float a[2][4];
#pragma unroll
        for (int i = 0; i < 2; ++i) {
            float4 t = *(float4*)(sS + (ty + 16 * i) * 128 + kk);
            a[i][0] = t.x; a[i][1] = t.y; a[i][2] = t.z; a[i][3] = t.w;
        }
#pragma unroll
        for (int q = 0; q < 4; ++q) {
            float4 b0 = *(float4*)(sW + (kk + q) * 128 + tx * 8);
            float4 b1v = *(float4*)(sW + (kk + q) * 128 + tx * 8 + 4);
            float bb[8] = {b0.x, b0.y, b0.z, b0.w, b1v.x, b1v.y, b1v.z, b1v.w};
#pragma unroll
            for (int i = 0; i < 2; ++i)
#pragma unroll
                for (int j = 0; j < 8; ++j) acc[i][j] += a[i][q] * bb[j];
        }
    }

    float xv[2][8];
    float4 b30 = *(const float4*)(b3 + tx * 8);
    float4 b31 = *(const float4*)(b3 + tx * 8 + 4);
    float b3v[8] = {b30.x, b30.y, b30.z, b30.w, b31.x, b31.y, b31.z, b31.w};
#pragma unroll
    for (int i = 0; i < 2; ++i) {
        int r = ty + 16 * i, n = n0 + r;
        float As = g_A[n];
        float4 nv0 = *(const float4*)(node + (size_t)n * 128 + tx * 8);
        float4 nv1 = *(const float4*)(node + (size_t)n * 128 + tx * 8 + 4);
        float nb[8] = {nv0.x, nv0.y, nv0.z, nv0.w, nv1.x, nv1.y, nv1.z, nv1.w};
        float s = 0.f, qq = 0.f;
#pragma unroll
        for (int j = 0; j < 8; ++j) {
            float v = nb[j] + (acc[i][j] + As * b3v[j]) * (1.0f / 30.0f);
            xv[i][j] = v; s += v; qq += v * v;
        }
        sRs[r * 16 + tx] = s;
        sRq[r * 16 + tx] = qq;
    }
    __syncthreads();
    float4 ga = *(const float4*)(g1 + tx * 8);
    float4 gb = *(const float4*)(g1 + tx * 8 + 4);
    float4 ea = *(const float4*)(be1 + tx * 8);
    float4 ebv = *(const float4*)(be1 + tx * 8 + 4);
    float gv[8] = {ga.x, ga.y, ga.z, ga.w, gb.x, gb.y, gb.z, gb.w};
    float ev[8] = {ea.x, ea.y, ea.z, ea.w, ebv.x, ebv.y, ebv.z, ebv.w};
#pragma unroll
    for (int i = 0; i < 2; ++i) {
        int r = ty + 16 * i;
        float s = 0.f, qq = 0.f;
#pragma unroll
        for (int t = 0; t < 16; ++t) { s += sRs[r * 16 + t]; qq += sRq[r * 16 + t]; }
        float mu = s * (1.0f / 128.0f);
        float var = qq * (1.0f / 128.0f) - mu * mu;
        float rs = rsqrtf(var + 1e-5f);
        float o[8];
#pragma unroll
        for (int j = 0; j < 8; ++j) o[j] = (xv[i][j] - mu) * rs * gv[j] + ev[j];
        *(float4*)(g_X + (size_t)(n0 + r) * 128 + tx * 8) = make_float4(o[0], o[1], o[2], o[3]);
        *(float4*)(g_X + (size_t)(n0 + r) * 128 + tx * 8 + 4) = make_float4(o[4], o[5], o[6], o[7]);
    }
}

// ============ K3: g_H = gelu(g_X @ Wd1^T + bd1)  (split over 4 h-tiles) ====
__global__ __launch_bounds__(256)
void k3_mlp1(const float* __restrict__ Wd1, const float* __restrict__ bd1) {
    extern __shared__ float sm[];
    float* sX = sm;          // 32*128
    float* sW = sm + 4096;   // 128*128: sW[k][h] = Wd1[(h0+h)*128 + k]
    const int tid = threadIdx.x, tx = tid & 15, ty = tid >> 4;
    const int n0 = blockIdx.x * 32;
    const int h0 = blockIdx.y * 128;

#pragma unroll
    for (int m = 0; m < 4; ++m) {
        int f4 = tid + 256 * m;
        int r = f4 >> 5, c4 = f4 & 31;
        *(float4*)(sX + r * 128 + c4 * 4) =
            *(const float4*)(g_X + (size_t)(n0 + r) * 128 + c4 * 4);
    }
#pragma unroll
    for (int m = 0; m < 16; ++m) {
        int idx = tid + 256 * m;
        int h = idx & 127, k4 = idx >> 7;
        float4 v = *(const float4*)(Wd1 + (size_t)(h0 + h) * 128 + k4 * 4);
        sW[(k4 * 4 + 0) * 128 + h] = v.x;
        sW[(k4 * 4 + 1) * 128 + h] = v.y;
        sW[(k4 * 4 + 2) * 128 + h] = v.z;
        sW[(k4 * 4 + 3) * 128 + h] = v.w;
    }
    __syncthreads();
    float acc[2][8] = {};
#pragma unroll
    for (int kk = 0; kk < 128; kk += 4) {
        float a[2][4];
#pragma unroll
        for (int i = 0; i < 2; ++i) {
            float4 t = *(float4*)(sX + (ty + 16 * i) * 128 + kk);
            a[i][0] = t.x; a[i][1] = t.y; a[i][2] = t.z; a[i][3] = t.w;
        }
#pragma unroll
        for (int q = 0; q < 4; ++q) {
            float4 b0 = *(float4*)(sW + (kk + q) * 128 + tx * 8);
            float4 b1v = *(float4*)(sW + (kk + q) * 128 + tx * 8 + 4);
            float bb[8] = {b0.x, b0.y, b0.z, b0.w, b1v.x, b1v.y, b1v.z, b1v.w};
#pragma unroll
            for (int i = 0; i < 2; ++i)
#pragma unroll
                for (int j = 0; j < 8; ++j) acc[i][j] += a[i][q] * bb[j];
        }
    }
#pragma unroll
    for (int i = 0; i < 2; ++i) {
        int r = n0 + ty + 16 * i;
#pragma unroll
        for (int j = 0; j < 8; ++j) {
            int h = h0 + tx * 8 + j;
            g_H[(size_t)r * 512 + h] = gelu_f(acc[i][j] + bd1[h]);
        }
    }
}

// ===== K4: out = mask * LN2(g_X + g_H @ Wd2^T + bd2)  (K=512, N=128) ========
__global__ __launch_bounds__(256)
void k4_out(const float* __restrict__ Wd2, const float* __restrict__ bd2,
            const float* __restrict__ g2, const float* __restrict__ be2,
            const float* __restrict__ maskp, float* __restrict__ out) {
    extern __shared__ float sm[];
    float* sA = sm;            // 32*128 (k-tile of g_H)
    float* sW = sm + 4096;     // 128*128: sW[k][c] = Wd2[c*512 + k0 + k]
    float* sRs = sm + 20480;   // 512
    float* sRq = sm + 20992;   // 512
    const int tid = threadIdx.x, tx = tid & 15, ty = tid >> 4;
    const int n0 = blockIdx.x * 32;

    float acc[2][8] = {};
    for (int k0 = 0; k0 < 512; k0 += 128) {
        __syncthreads();
#pragma unroll
        for (int m = 0; m < 4; ++m) {
            int f4 = tid + 256 * m;
            int r = f4 >> 5, c4 = f4 & 31;
            *(float4*)(sA + r * 128 + c4 * 4) =
                *(const float4*)(g_H + (size_t)(n0 + r) * 512 + k0 + c4 * 4);
        }
#pragma unroll
        for (int m = 0; m < 16; ++m) {
            int idx = tid + 256 * m;
            int c = idx & 127, k4 = idx >> 7;
            float4 v = *(const float4*)(Wd2 + (size_t)c * 512 + k0 + k4 * 4);
            sW[(k4 * 4 + 0) * 128 + c] = v.x;
            sW[(k4 * 4 + 1) * 128 + c] = v.y;
            sW[(k4 * 4 + 2) * 128 + c] = v.z;
            sW[(k4 * 4 + 3) * 128 + c] = v.w;
        }
        __syncthreads();
#pragma unroll
        for (int kk = 0; kk < 128; kk += 4) {
            float a[2][4];
#pragma unroll
            for (int i = 0; i < 2; ++i) {
                float4 t = *(float4*)(sA + (ty + 16 * i) * 128 + kk);
                a[i][0] = t.x; a[i][1] = t.y; a[i][2] = t.z; a[i][3] = t.w;
            }
#pragma unroll
            for (int q = 0; q < 4; ++q) {
                float4 b0 = *(float4*)(sW + (kk + q) * 128 + tx * 8);
                float4 b1v = *(float4*)(sW + (kk + q) * 128 + tx * 8 + 4);
                float bb[8] = {b0.x, b0.y, b0.z, b0.w, b1v.x, b1v.y, b1v.z, b1v.w};
#pragma unroll
                for (int i = 0; i < 2; ++i)
#pragma unroll
                    for (int j = 0; j < 8; ++j) acc[i][j] += a[i][q] * bb[j];
            }
        }
    }

    float xv[2][8];
    float4 ba = *(const float4*)(bd2 + tx * 8);
    float4 bbv = *(const float4*)(bd2 + tx * 8 + 4);
    float bdv[8] = {ba.x, ba.y, ba.z, ba.w, bbv.x, bbv.y, bbv.z, bbv.w};
#pragma unroll
    for (int i = 0; i < 2; ++i) {
        int r = ty + 16 * i, n = n0 + r;
        float4 x0 = *(const float4*)(g_X + (size_t)n * 128 + tx * 8);
        float4 x1 = *(const float4*)(g_X + (size_t)n * 128 + tx * 8 + 4);
        float xb[8] = {x0.x, x0.y, x0.z, x0.w, x1.x, x1.y, x1.z, x1.w};
        float s = 0.f, qq = 0.f;
#pragma unroll
        for (int j = 0; j < 8; ++j) {
            float v = xb[j] + acc[i][j] + bdv[j];
            xv[i][j] = v; s += v; qq += v * v;
        }
        sRs[r * 16 + tx] = s;
        sRq[r * 16 + tx] = qq;
    }
    __syncthreads();
    float4 ga = *(const float4*)(g2 + tx * 8);
    float4 gb = *(const float4*)(g2 + tx * 8 + 4);
    float4 ea = *(const float4*)(be2 + tx * 8);
    float4 ebv = *(const float4*)(be2 + tx * 8 + 4);
    float gv[8] = {ga.x, ga.y, ga.z, ga.w, gb.x, gb.y, gb.z, gb.w};
    float ev[8] = {ea.x, ea.y, ea.z, ea.w, ebv.x, ebv.y, ebv.z, ebv.w};
#pragma unroll
    for (int i = 0; i < 2; ++i) {
        int r = ty + 16 * i, n = n0 + r;
        float s = 0.f, qq = 0.f;
#pragma unroll
        for (int t = 0; t < 16; ++t) { s += sRs[r * 16 + t]; qq += sRq[r * 16 + t]; }
        float mu = s * (1.0f / 128.0f);
        float var = qq * (1.0f / 128.0f) - mu * mu;
        float rs = rsqrtf(var + 1e-5f);
        float mk = maskp[n];
        float o[8];
#pragma unroll
        for (int j = 0; j < 8; ++j)
            o[j] = mk * ((xv[i][j] - mu) * rs * gv[j] + ev[j]);
        *(float4*)(out + (size_t)n * 128 + tx * 8) = make_float4(o[0], o[1], o[2], o[3]);
        *(float4*)(out + (size_t)n * 128 + tx * 8 + 4) = make_float4(o[4], o[5], o[6], o[7]);
    }
}

// ============================== launch =====================================
extern "C" void kernel_launch(void* const* d_in, const int* in_sizes, int n_in,
                              void* d_out, int out_size) {
    const float* node = (const float*)d_in[0];
    const float* edge = (const float*)d_in[1];
    const float* mask = (const float*)d_in[2];
    const float* attn = (const float*)d_in[3];
    const float* W1   = (const float*)d_in[4];
    const float* b1   = (const float*)d_in[5];
    const float* W2   = (const float*)d_in[6];
    const float* b2   = (const float*)d_in[7];
    const float* W3   = (const float*)d_in[8];
    const float* b3   = (const float*)d_in[9];
    const float* g1   = (const float*)d_in[10];
    const float* be1  = (const float*)d_in[11];
    const float* Wd1  = (const float*)d_in[12];
    const float* bd1  = (const float*)d_in[13];
    const float* Wd2  = (const float*)d_in[14];
    const float* bd2  = (const float*)d_in[15];
    const float* g2   = (const float*)d_in[16];
    const float* be2  = (const float*)d_in[17];
    float* out = (float*)d_out;

    const size_t s0 = (size_t)(4096 + 16384) * sizeof(float);
    const size_t s1 = (size_t)S1_WORDS * sizeof(unsigned);
    const size_t s2 = (size_t)(4096 + 16384 + 512 + 512) * sizeof(float);
    const size_t s3 = (size_t)(4096 + 16384) * sizeof(float);
    const size_t s4 = (size_t)(4096 + 16384 + 512 + 512) * sizeof(float);

    cudaFuncSetAttribute(k0_node_pre, cudaFuncAttributeMaxDynamicSharedMemorySize, (int)s0);
    cudaFuncSetAttribute(k1_edges,    cudaFuncAttributeMaxDynamicSharedMemorySize, (int)s1);
    cudaFuncSetAttribute(k2_ln1,      cudaFuncAttributeMaxDynamicSharedMemorySize, (int)s2);
    cudaFuncSetAttribute(k3_mlp1,     cudaFuncAttributeMaxDynamicSharedMemorySize, (int)s3);
    cudaFuncSetAttribute(k4_out,      cudaFuncAttributeMaxDynamicSharedMemorySize, (int)s4);

    k_prep<<<128, 256>>>(W1, W2);
    k0_node_pre<<<NN / 32, 256, s0>>>(node, W1, b1);
    k1_edges<<<NN / 2, 256, s1>>>(edge, attn, b2);
    k2_ln1<<<NN / 32, 256, s2>>>(node, W3, b3, g1, be1);
    k3_mlp1<<<dim3(NN / 32, 4), 256, s3>>>(Wd1, bd1);
    k4_out<<<NN / 32, 256, s4>>>(Wd2, bd2, g2, be2, mask, out);
}

// round 11
// speedup vs baseline: 1.1194x; 1.1194x over previous
#include <cuda_runtime.h>
#include <cuda_bf16.h>
#include <math.h>

#define NN 4096
#define KN 48
#define CC 128
#define EC 384
#define HD 512

// ---------------- scratch (device globals: allocation-free) ----------------
__device__ float g_node_pre[NN * CC];   // node @ W1a^T + b_m1
__device__ float g_S[NN * CC];          // sum_k attn * h2
__device__ float g_A[NN];               // sum_k attn
__device__ unsigned g_Wp1[192 * 128];   // W1b^T packed bf16x2 along k: [kk][c]
__device__ unsigned g_Wp2[64 * 128];    // W2^T  packed bf16x2 along k: [kk][c]

__device__ __forceinline__ float gelu_f(float x) {
    return 0.5f * x * (1.0f + erff(x * 0.70710678118654752440f));
}

__device__ __forceinline__ unsigned pk(float a, float b) {
    __nv_bfloat162 t = __floats2bfloat162_rn(a, b);
    return *(unsigned*)&t;
}

__device__ __forceinline__ void mma_bf16(float c[4], const unsigned a[4], const unsigned b[2]) {
    asm volatile(
        "mma.sync.aligned.m16n8k16.row.col.f32.bf16.bf16.f32 "
        "{%0,%1,%2,%3},{%4,%5,%6,%7},{%8,%9},{%0,%1,%2,%3};\n"
        : "+f"(c[0]), "+f"(c[1]), "+f"(c[2]), "+f"(c[3])
        : "r"(a[0]), "r"(a[1]), "r"(a[2]), "r"(a[3]), "r"(b[0]), "r"(b[1]));
}

// =================== Kprep: pack weights to bf16x2 (k-major) ===============
__global__ __launch_bounds__(256)
void k_prep(const float* __restrict__ W1, const float* __restrict__ W2) {
    int idx = blockIdx.x * 256 + threadIdx.x;
    if (idx < 192 * 128) {
        int kk = idx >> 7, c = idx & 127;
        g_Wp1[idx] = pk(W1[(size_t)c * 512 + 128 + 2 * kk],
                        W1[(size_t)c * 512 + 128 + 2 * kk + 1]);
    } else if (idx < 192 * 128 + 64 * 128) {
        int j = idx - 192 * 128;
        int kk = j >> 7, c = j & 127;
        g_Wp2[j] = pk(W2[(size_t)c * 128 + 2 * kk],
                      W2[(size_t)c * 128 + 2 * kk + 1]);
    }
}

// ======================= K0: node_pre = node @ W1a^T + b1 ==================
__global__ __launch_bounds__(256)
void k0_node_pre(const float* __restrict__ node, const float* __restrict__ W1,
                 const float* __restrict__ b1) {
    extern __shared__ float sm[];
    float* sX = sm;           // 32*128
    float* sW = sm + 4096;    // 128*128  sW[k][c] = W1[c*512 + k]
    const int tid = threadIdx.x, tx = tid & 15, ty = tid >> 4;
    const int n0 = blockIdx.x * 32;

#pragma unroll
    for (int m = 0; m < 4; ++m) {
        int f4 = tid + 256 * m;
        int r = f4 >> 5, c4 = f4 & 31;
        *(float4*)(sX + r * 128 + c4 * 4) =
            *(const float4*)(node + (size_t)(n0 + r) * 128 + c4 * 4);
    }
#pragma unroll
    for (int m = 0; m < 16; ++m) {
        int idx = tid + 256 * m;
        int c = idx & 127, k4 = idx >> 7;
        float4 v = *(const float4*)(W1 + (size_t)c * 512 + k4 * 4);
        sW[(k4 * 4 + 0) * 128 + c] = v.x;
        sW[(k4 * 4 + 1) * 128 + c] = v.y;
        sW[(k4 * 4 + 2) * 128 + c] = v.z;
        sW[(k4 * 4 + 3) * 128 + c] = v.w;
    }
    __syncthreads();

    float acc[2][8] = {};
#pragma unroll
    for (int kk = 0; kk < 128; kk += 4) {
        float a[2][4];
#pragma unroll
        for (int i = 0; i < 2; ++i) {
            float4 t = *(float4*)(sX + (ty + 16 * i) * 128 + kk);
            a[i][0] = t.x; a[i][1] = t.y; a[i][2] = t.z; a[i][3] = t.w;
        }
#pragma unroll
        for (int q = 0; q < 4; ++q) {
            float4 b0 = *(float4*)(sW + (kk + q) * 128 + tx * 8);
            float4 b1v = *(float4*)(sW + (kk + q) * 128 + tx * 8 + 4);
            float bb[8] = {b0.x, b0.y, b0.z, b0.w, b1v.x, b1v.y, b1v.z, b1v.w};
#pragma unroll
            for (int i = 0; i < 2; ++i)
#pragma unroll
                for (int j = 0; j < 8; ++j) acc[i][j] += a[i][q] * bb[j];
        }
    }
#pragma unroll
    for (int i = 0; i < 2; ++i) {
        int r = n0 + ty + 16 * i;
#pragma unroll
        for (int j = 0; j < 8; ++j) {
            int c = tx * 8 + j;
            g_node_pre[(size_t)r * 128 + c] = acc[i][j] + b1[c];
        }
    }
}

// ================ K1: per-node-pair edge message kernel (bf16 MMA) =========
// R8 version (measured-fast): scalar-LDS fragments, single-buffered k-tiles.
#define SA_OFF 0            // 96 * 36 u32 (edge tile, bf16x2, pad 36)
#define SB_OFF 3456         // 64 * 136 u32 (weight tile, bf16x2, pad 136)
#define SH_OFF 12160        // 96 * 68 u32 (h1 bf16x2, pad 68)
#define SNP_OFF 18688       // 256 f (node_pre, 2 nodes)
#define SAT_OFF 18944       // 96 f (attn)
#define SB2_OFF 19040       // 128 f (b2)
#define S1_WORDS 19168

__global__ __launch_bounds__(256, 2)
void k1_edges(const float* __restrict__ edge, const float* __restrict__ attn,
              const float* __restrict__ b2) {
    extern __shared__ unsigned smu[];
    unsigned* sA = smu + SA_OFF;
    unsigned* sB = smu + SB_OFF;
    unsigned* sH = smu + SH_OFF;
    float* sNP = (float*)(smu + SNP_OFF);
    float* sAt = (float*)(smu + SAT_OFF);
    float* sb2 = (float*)(smu + SB2_OFF);

    const int tid = threadIdx.x;
    const int lane = tid & 31, wid = tid >> 5;
    const int mg = wid >> 2;        // node within block (0,1)
    const int ng = wid & 3;         // n32 column group
    const int g = lane >> 2, q = lane & 3;
    const int n0 = blockIdx.x * 2;
    const float* eb = edge + (size_t)n0 * (KN * EC);

    if (tid < 256) sNP[tid] = g_node_pre[(size_t)n0 * 128 + tid];
    if (tid < 96) sAt[tid] = attn[(size_t)n0 * KN + tid];
    if (tid < 128) sb2[tid] = b2[tid];

    float acc[3][4][4] = {};

    // ---------------- GEMM1b over edge context: 6 k-tiles of 64 ------------
    for (int kt = 0; kt < 6; ++kt) {
        __syncthreads();
#pragma unroll
        for (int m = 0; m < 6; ++m) {
            int f = tid + 256 * m;
            int row = f >> 4, c4 = f & 15;
            float4 v = *(const float4*)(eb + (size_t)row * EC + kt * 64 + c4 * 4);
            *(uint2*)(sA + row * 36 + c4 * 2) =
                make_uint2(pk(v.x, v.y), pk(v.z, v.w));
        }
#pragma unroll
        for (int m = 0; m < 4; ++m) {
            int f = tid + 256 * m;
            int kk = f >> 5, c4 = f & 31;
            *(uint4*)(sB + kk * 136 + c4 * 4) =
                *(const uint4*)(g_Wp1 + (size_t)(kt * 32 + kk) * 128 + c4 * 4);
        }
        __syncthreads();
#pragma unroll
        for (int s = 0; s < 4; ++s) {
            unsigned a[3][4], bf[4][2];
#pragma unroll
            for (int mi = 0; mi < 3; ++mi) {
                const unsigned* base = sA + (mg * 48 + mi * 16 + g) * 36 + s * 8 + q;
                a[mi][0] = base[0];
                a[mi][1] = base[8 * 36];
                a[mi][2] = base[4];
                a[mi][3] = base[8 * 36 + 4];
            }
#pragma unroll
            for (int t = 0; t < 4; ++t) {
                int n = ng * 32 + t * 8 + g;
                bf[t][0] = sB[(s * 8 + q) * 136 + n];
                bf[t][1] = sB[(s * 8 + 4 + q) * 136 + n];
            }
#pragma unroll
            for (int mi = 0; mi < 3; ++mi)
#pragma unroll
                for (int t = 0; t < 4; ++t) mma_bf16(acc[mi][t], a[mi], bf[t]);
        }
    }

    // ---- epilogue 1: h1 = gelu(node_pre + acc) -> sH (bf16x2) -------------
#pragma unroll
    for (int mi = 0; mi < 3; ++mi) {
        int r0 = mg * 48 + mi * 16 + g;
#pragma unroll
        for (int t = 0; t < 4; ++t) {
            int c = ng * 32 + t * 8 + 2 * q;
            float np0 = sNP[mg * 128 + c], np1 = sNP[mg * 128 + c + 1];
            unsigned lo = pk(gelu_f(acc[mi][t][0] + np0), gelu_f(acc[mi][t][1] + np1));
            unsigned hi = pk(gelu_f(acc[mi][t][2] + np0), gelu_f(acc[mi][t][3] + np1));
            sH[r0 * 68 + ng * 16 + t * 4 + q] = lo;
            sH[(r0 + 8) * 68 + ng * 16 + t * 4 + q] = hi;
            acc[mi][t][0] = acc[mi][t][1] = acc[mi][t][2] = acc[mi][t][3] = 0.f;
        }
    }
    __syncthreads();

    // ---- load W2^T packed into sB (64 kk x 128; 2048 uint4 / 256 = 8) -----
#pragma unroll
    for (int m = 0; m < 8; ++m) {
        int f = tid + 256 * m;
        int kk = f >> 5, c4 = f & 31;
        *(uint4*)(sB + kk * 136 + c4 * 4) =
            *(const uint4*)(g_Wp2 + (size_t)kk * 128 + c4 * 4);
    }
    if (tid < 2) {
        float s = 0.f;
#pragma unroll
        for (int k = 0; k < KN; ++k) s += sAt[tid * KN + k];
        g_A[n0 + tid] = s;
    }
    __syncthreads();

    // ---------------- GEMM2: h1 @ W2^T (8 k16 steps) -----------------------
#pragma unroll
    for (int s = 0; s < 8; ++s) {
        unsigned a[3][4], bf[4][2];
#pragma unroll
        for (int mi = 0; mi < 3; ++mi) {
            const unsigned* base = sH + (mg * 48 + mi * 16 + g) * 68 + s * 8 + q;
            a[mi][0] = base[0];
            a[mi][1] = base[8 * 68];
            a[mi][2] = base[4];
            a[mi][3] = base[8 * 68 + 4];
        }
#pragma unroll
        for (int t = 0; t < 4; ++t) {
            int n = ng * 32 + t * 8 + g;
            bf[t][0] = sB[(s * 8 + q) * 136 + n];
            bf[t][1] = sB[(s * 8 + 4 + q) * 136 + n];
        }
#pragma unroll
        for (int mi = 0; mi < 3; ++mi)
#pragma unroll
            for (int t = 0; t < 4; ++t) mma_bf16(acc[mi][t], a[mi], bf[t]);
    }

    // ---- epilogue 2: gelu(+b2), attn-weighted reduce over the 48 rows -----
#pragma unroll
    for (int t = 0; t < 4; ++t) {
        int c = ng * 32 + t * 8 + 2 * q;
        float bc0 = sb2[c], bc1 = sb2[c + 1];
        float p0 = 0.f, p1 = 0.f;
#pragma unroll
        for (int mi = 0; mi < 3; ++mi) {
            int r0 = mi * 16 + g;
            float w0 = sAt[mg * 48 + r0];
            float w1 = sAt[mg * 48 + r0 + 8];
            p0 += w0 * gelu_f(acc[mi][t][0] + bc0) + w1 * gelu_f(acc[mi][t][2] + bc0);
            p1 += w0 * gelu_f(acc[mi][t][1] + bc1) + w1 * gelu_f(acc[mi][t][3] + bc1);
        }
#pragma unroll
        for (int off = 16; off >= 4; off >>= 1) {
            p0 += __shfl_xor_sync(0xffffffffu, p0, off);
            p1 += __shfl_xor_sync(0xffffffffu, p1, off);
        }
        if (lane < 4) {
            int cc = ng * 32 + t * 8 + 2 * lane;
            g_S[(size_t)(n0 + mg) * 128 + cc] = p0;
            g_S[(size_t)(n0 + mg) * 128 + cc + 1] = p1;
        }
    }
}

// ====== K234: fused  x=LN1(node+(W3@S+A*b3)/30); H=gelu(x@Wd1^T+bd1);
//              out = mask*LN2(x + H@Wd2^T + bd2).   16 nodes/block ==========
#define T4_WORDS 27136
__global__ __launch_bounds__(256)
void k234(const float* __restrict__ node, const float* __restrict__ W3,
          const float* __restrict__ b3, const float* __restrict__ g1,
          const float* __restrict__ be1,
          const float* __restrict__ Wd1, const float* __restrict__ bd1,
          const float* __restrict__ Wd2, const float* __restrict__ bd2,
          const float* __restrict__ g2, const float* __restrict__ be2,
          const float* __restrict__ maskp, float* __restrict__ out) {
    extern __shared__ float sm[];
    float* sW = sm;            // 16384: current weight tile [k][c] (transposed)
    float* sX = sm + 16384;    // 2048: x (16 x 128)
    float* sH = sm + 18432;    // 8192: H (16 x 512); phase-A: S tile (16x128)
    float* sRs = sm + 26624;   // 256
    float* sRq = sm + 26880;   // 256
    const int tid = threadIdx.x, tx = tid & 15, ty = tid >> 4;
    const int n0 = blockIdx.x * 16;
    const int n = n0 + ty;

    // ---------------- phase A: x = LN1(node + (W3@S + A*b3)/30) ------------
#pragma unroll
    for (int m = 0; m < 2; ++m) {
        int f = tid + 256 * m;
        int r = f >> 5, c4 = f & 31;
        *(float4*)(sH + r * 128 + c4 * 4) =
            *(const float4*)(g_S + (size_t)(n0 + r) * 128 + c4 * 4);
    }
#pragma unroll
    for (int m = 0; m < 16; ++m) {
        int idx = tid + 256 * m;
        int d = idx & 127, c4 = idx >> 7;
        float4 v = *(const float4*)(W3 + (size_t)d * 128 + c4 * 4);
        sW[(c4 * 4 + 0) * 128 + d] = v.x;
        sW[(c4 * 4 + 1) * 128 + d] = v.y;
        sW[(c4 * 4 + 2) * 128 + d] = v.z;
        sW[(c4 * 4 + 3) * 128 + d] = v.w;
    }
    __syncthreads();

    float acc[8] = {};
#pragma unroll
    for (int kk = 0; kk < 128; kk += 4) {
        float4 t = *(float4*)(sH + ty * 128 + kk);
        float a[4] = {t.x, t.y, t.z, t.w};
#pragma unroll
        for (int qq = 0; qq < 4; ++qq) {
            float4 b0 = *(float4*)(sW + (kk + qq) * 128 + tx * 8);
            float4 b1 = *(float4*)(sW + (kk + qq) * 128 + tx * 8 + 4);
            float bb[8] = {b0.x, b0.y, b0.z, b0.w, b1.x, b1.y, b1.z, b1.w};
#pragma unroll
            for (int j = 0; j < 8; ++j) acc[j] += a[qq] * bb[j];
        }
    }

    float xv[8];
    {
        float As = g_A[n];
        float4 b30 = *(const float4*)(b3 + tx * 8);
        float4 b31 = *(const float4*)(b3 + tx * 8 + 4);
        float b3v[8] = {b30.x, b30.y, b30.z, b30.w, b31.x, b31.y, b31.z, b31.w};
        float4 nv0 = *(const float4*)(node + (size_t)n * 128 + tx * 8);
        float4 nv1 = *(const float4*)(node + (size_t)n * 128 + tx * 8 + 4);
        float nb[8] = {nv0.x, nv0.y, nv0.z, nv0.w, nv1.x, nv1.y, nv1.z, nv1.w};
        float s = 0.f, qs = 0.f;
#pragma unroll
        for (int j = 0; j < 8; ++j) {
            float v = nb[j] + (acc[j] + As * b3v[j]) * (1.0f / 30.0f);
            xv[j] = v; s += v; qs += v * v;
        }
        sRs[ty * 16 + tx] = s;
        sRq[ty * 16 + tx] = qs;
    }
    __syncthreads();
    {
        float s = 0.f, qs = 0.f;
#pragma unroll
        for (int t = 0; t < 16; ++t) { s += sRs[ty * 16 + t]; qs += sRq[ty * 16 + t]; }
        float mu = s * (1.0f / 128.0f);
        float var = qs * (1.0f / 128.0f) - mu * mu;
        float rs = rsqrtf(var + 1e-5f);
        float4 ga = *(const float4*)(g1 + tx * 8);
        float4 gb = *(const float4*)(g1 + tx * 8 + 4);
        float4 ea = *(const float4*)(be1 + tx * 8);
        float4 eb2 = *(const float4*)(be1 + tx * 8 + 4);
        float gv[8] = {ga.x, ga.y, ga.z, ga.w, gb.x, gb.y, gb.z, gb.w};
        float ev[8] = {ea.x, ea.y, ea.z, ea.w, eb2.x, eb2.y, eb2.z, eb2.w};
#pragma unroll
        for (int j = 0; j < 8; ++j) xv[j] = (xv[j] - mu) * rs * gv[j] + ev[j];
        *(float4*)(sX + ty * 128 + tx * 8) = make_float4(xv[0], xv[1], xv[2], xv[3]);
        *(float4*)(sX + ty * 128 + tx * 8 + 4) = make_float4(xv[4], xv[5], xv[6], xv[7]);
    }
    __syncthreads();

    // ---------------- phase B: H = gelu(x @ Wd1^T + bd1) -------------------
    for (int t = 0; t < 4; ++t) {
        int h0 = t * 128;
#pragma unroll
        for (int m = 0; m < 16; ++m) {
            int idx = tid + 256 * m;
            int h = idx & 127, k4 = idx >> 7;
            float4 v = *(const float4*)(Wd1 + (size_t)(h0 + h) * 128 + k4 * 4);
            sW[(k4 * 4 + 0) * 128 + h] = v.x;
            sW[(k4 * 4 + 1) * 128 + h] = v.y;
            sW[(k4 * 4 + 2) * 128 + h] = v.z;
            sW[(k4 * 4 + 3) * 128 + h] = v.w;
        }
        __syncthreads();
        float a2[8] = {};
#pragma unroll
        for (int kk = 0; kk < 128; kk += 4) {
            float4 tt = *(float4*)(sX + ty * 128 + kk);
            float a[4] = {tt.x, tt.y, tt.z, tt.w};
#pragma unroll
            for (int qq = 0; qq < 4; ++qq) {
                float4 b0 = *(float4*)(sW + (kk + qq) * 128 + tx * 8);
                float4 b1 = *(float4*)(sW + (kk + qq) * 128 + tx * 8 + 4);
                float bb[8] = {b0.x, b0.y, b0.z, b0.w, b1.x, b1.y, b1.z, b1.w};
#pragma unroll
                for (int j = 0; j < 8; ++j) a2[j] += a[qq] * bb[j];
            }
        }
#pragma unroll
        for (int j = 0; j < 8; ++j) {
            int h = h0 + tx * 8 + j;
            sH[ty * 512 + h] = gelu_f(a2[j] + bd1[h]);
        }
        __syncthreads();
    }

    // ---------------- phase C: out = mask*LN2(x + H @ Wd2^T + bd2) ---------
    float acc3[8] = {};
    for (int t = 0; t < 4; ++t) {
        int k0 = t * 128;
#pragma unroll
        for (int m = 0; m < 16; ++m) {
            int idx = tid + 256 * m;
            int c = idx & 127, k4 = idx >> 7;
            float4 v = *(const float4*)(Wd2 + (size_t)c * 512 + k0 + k4 * 4);
            sW[(k4 * 4 + 0) * 128 + c] = v.x;
            sW[(k4 * 4 + 1) * 128 + c] = v.y;
            sW[(k4 * 4 + 2) * 128 + c] = v.z;
            sW[(k4 * 4 + 3) * 128 + c] = v.w;
        }
        __syncthreads();
#pragma unroll
        for (int kk = 0; kk < 128; kk += 4) {
            float4 tt = *(float4*)(sH + ty * 512 + k0 + kk);
            float a[4] = {tt.x, tt.y, tt.z, tt.w};
#pragma unroll
            for (int qq = 0; qq < 4; ++qq) {
                float4 b0 = *(float4*)(sW + (kk + qq) * 128 + tx * 8);
                float4 b1 = *(float4*)(sW + (kk + qq) * 128 + tx * 8 + 4);
                float bb[8] = {b0.x, b0.y, b0.z, b0.w, b1.x, b1.y, b1.z, b1.w};
#pragma unroll
                for (int j = 0; j < 8; ++j) acc3[j] += a[qq] * bb[j];
            }
        }
        __syncthreads();
    }

    {
        float4 ba = *(const float4*)(bd2 + tx * 8);
        float4 bbv = *(const float4*)(bd2 + tx * 8 + 4);
        float bdv[8] = {ba.x, ba.y, ba.z, ba.w, bbv.x, bbv.y, bbv.z, bbv.w};
        float4 x0 = *(float4*)(sX + ty * 128 + tx * 8);
        float4 x1 = *(float4*)(sX + ty * 128 + tx * 8 + 4);
        float xb[8] = {x0.x, x0.y, x0.z, x0.w, x1.x, x1.y, x1.z, x1.w};
        float vv[8];
        float s = 0.f, qs = 0.f;
#pragma unroll
        for (int j = 0; j < 8; ++j) {
            float v = xb[j] + acc3[j] + bdv[j];
            vv[j] = v; s += v; qs += v * v;
        }
        sRs[ty * 16 + tx] = s;
        sRq[ty * 16 + tx] = qs;
        __syncthreads();
        s = 0.f; qs = 0.f;
#pragma unroll
        for (int t = 0; t < 16; ++t) { s += sRs[ty * 16 + t]; qs += sRq[ty * 16 + t]; }
        float mu = s * (1.0f / 128.0f);
        float var = qs * (1.0f / 128.0f) - mu * mu;
        float rs = rsqrtf(var + 1e-5f);
        float mk = maskp[n];
        float4 ga = *(const float4*)(g2 + tx * 8);
        float4 gb = *(const float4*)(g2 + tx * 8 + 4);
        float4 ea = *(const float4*)(be2 + tx * 8);
        float4 eb2 = *(const float4*)(be2 + tx * 8 + 4);
        float gv[8] = {ga.x, ga.y, ga.z, ga.w, gb.x, gb.y, gb.z, gb.w};
        float ev[8] = {ea.x, ea.y, ea.z, ea.w, eb2.x, eb2.y, eb2.z, eb2.w};
        float o[8];
#pragma unroll
        for (int j = 0; j < 8; ++j)
            o[j] = mk * ((vv[j] - mu) * rs * gv[j] + ev[j]);
        *(float4*)(out + (size_t)n * 128 + tx * 8) = make_float4(o[0], o[1], o[2], o[3]);
        *(float4*)(out + (size_t)n * 128 + tx * 8 + 4) = make_float4(o[4], o[5], o[6], o[7]);
    }
}

// ============================== launch =====================================
extern "C" void kernel_launch(void* const* d_in, const int* in_sizes, int n_in,
                              void* d_out, int out_size) {
    const float* node = (const float*)d_in[0];
    const float* edge = (const float*)d_in[1];
    const float* mask = (const float*)d_in[2];
    const float* attn = (const float*)d_in[3];
    const float* W1   = (const float*)d_in[4];
    const float* b1   = (const float*)d_in[5];
    const float* W2   = (const float*)d_in[6];
    const float* b2   = (const float*)d_in[7];
    const float* W3   = (const float*)d_in[8];
    const float* b3   = (const float*)d_in[9];
    const float* g1   = (const float*)d_in[10];
    const float* be1  = (const float*)d_in[11];
    const float* Wd1  = (const float*)d_in[12];
    const float* bd1  = (const float*)d_in[13];
    const float* Wd2  = (const float*)d_in[14];
    const float* bd2  = (const float*)d_in[15];
    const float* g2   = (const float*)d_in[16];
    const float* be2  = (const float*)d_in[17];
    float* out = (float*)d_out;

    const size_t s0 = (size_t)(4096 + 16384) * sizeof(float);
    const size_t s1 = (size_t)S1_WORDS * sizeof(unsigned);
    const size_t s4 = (size_t)T4_WORDS * sizeof(float);

    cudaFuncSetAttribute(k0_node_pre, cudaFuncAttributeMaxDynamicSharedMemorySize, (int)s0);
    cudaFuncSetAttribute(k1_edges,    cudaFuncAttributeMaxDynamicSharedMemorySize, (int)s1);
    cudaFuncSetAttribute(k234,        cudaFuncAttributeMaxDynamicSharedMemorySize, (int)s4);

    k_prep<<<128, 256>>>(W1, W2);
    k0_node_pre<<<NN / 32, 256, s0>>>(node, W1, b1);
    k1_edges<<<NN / 2, 256, s1>>>(edge, attn, b2);
    k234<<<NN / 16, 256, s4>>>(node, W3, b3, g1, be1, Wd1, bd1,
                               Wd2, bd2, g2, be2, mask, out);
}

// round 13
// speedup vs baseline: 2.1480x; 1.9188x over previous
#include <cuda_runtime.h>
#include <cuda_bf16.h>
#include <math.h>

#define NN 4096
#define KN 48
#define CC 128
#define EC 384
#define HD 512

// ---------------- scratch (device globals: allocation-free) ----------------
__device__ float g_node_pre[NN * CC];   // node @ W1a^T + b_m1
__device__ float g_S[NN * CC];          // sum_k attn * h2
__device__ float g_A[NN];               // sum_k attn
__device__ unsigned g_Wp1[192 * 128];   // W1b^T packed bf16x2 along k: [kk][c]
__device__ unsigned g_Wp2[64 * 128];    // W2^T  packed bf16x2 along k: [kk][c]
__device__ unsigned g_Wp3[64 * 128];    // W3    packed bf16x2: [kk][d]
__device__ unsigned g_WpD1[256 * 128];  // Wd1   packed: [t*64+kk][h_local]
__device__ unsigned g_WpD2[256 * 128];  // Wd2   packed: [kt*64+kk][c]

__device__ __forceinline__ float gelu_f(float x) {
    return 0.5f * x * (1.0f + erff(x * 0.70710678118654752440f));
}

__device__ __forceinline__ unsigned pk(float a, float b) {
    __nv_bfloat162 t = __floats2bfloat162_rn(a, b);
    return *(unsigned*)&t;
}

__device__ __forceinline__ void mma_bf16(float c[4], const unsigned a[4], const unsigned b[2]) {
    asm volatile(
        "mma.sync.aligned.m16n8k16.row.col.f32.bf16.bf16.f32 "
        "{%0,%1,%2,%3},{%4,%5,%6,%7},{%8,%9},{%0,%1,%2,%3};\n"
        : "+f"(c[0]), "+f"(c[1]), "+f"(c[2]), "+f"(c[3])
        : "r"(a[0]), "r"(a[1]), "r"(a[2]), "r"(a[3]), "r"(b[0]), "r"(b[1]));
}

// 32xN(=128)xK(=128) block-GEMM step: A bf16x2 [32][astride], B bf16x2 [64][136]
__device__ __forceinline__ void gemm32(const unsigned* sA, int astride,
                                       const unsigned* sB, int mg, int ng,
                                       int lane, float acc[4][4]) {
    const int g = lane >> 2, q = lane & 3;
#pragma unroll
    for (int s = 0; s < 8; ++s) {
        unsigned a[4], bf[4][2];
        const unsigned* base = sA + (mg * 16 + g) * astride + s * 8 + q;
        a[0] = base[0];
        a[1] = base[8 * astride];
        a[2] = base[4];
        a[3] = base[8 * astride + 4];
#pragma unroll
        for (int t = 0; t < 4; ++t) {
            int n = ng * 32 + t * 8 + g;
            bf[t][0] = sB[(s * 8 + q) * 136 + n];
            bf[t][1] = sB[(s * 8 + 4 + q) * 136 + n];
        }
#pragma unroll
        for (int t = 0; t < 4; ++t) mma_bf16(acc[t], a, bf[t]);
    }
}

// =================== Kprep: pack ALL weights to bf16x2 =====================
__global__ __launch_bounds__(256)
void k_prep(const float* __restrict__ W1, const float* __restrict__ W2,
            const float* __restrict__ W3, const float* __restrict__ Wd1,
            const float* __restrict__ Wd2) {
    int idx = blockIdx.x * 256 + threadIdx.x;
    if (idx < 24576) {                       // g_Wp1: 192*128
        int kk = idx >> 7, c = idx & 127;
        g_Wp1[idx] = pk(W1[(size_t)c * 512 + 128 + 2 * kk],
                        W1[(size_t)c * 512 + 128 + 2 * kk + 1]);
    } else if (idx < 32768) {                // g_Wp2: 64*128
        int j = idx - 24576;
        int kk = j >> 7, c = j & 127;
        g_Wp2[j] = pk(W2[(size_t)c * 128 + 2 * kk],
                      W2[(size_t)c * 128 + 2 * kk + 1]);
    } else if (idx < 40960) {                // g_Wp3: 64*128
        int j = idx - 32768;
        int kk = j >> 7, d = j & 127;
        g_Wp3[j] = pk(W3[(size_t)d * 128 + 2 * kk],
                      W3[(size_t)d * 128 + 2 * kk + 1]);
    } else if (idx < 73728) {                // g_WpD1: 256*128
        int j = idx - 40960;
        int row = j >> 7, hh = j & 127;
        int t = row >> 6, kk = row & 63;
        g_WpD1[j] = pk(Wd1[(size_t)(t * 128 + hh) * 128 + 2 * kk],
                       Wd1[(size_t)(t * 128 + hh) * 128 + 2 * kk + 1]);
    } else if (idx < 106496) {               // g_WpD2: 256*128
        int j = idx - 73728;
        int row = j >> 7, c = j & 127;
        int kt = row >> 6, kk = row & 63;
        g_WpD2[j] = pk(Wd2[(size_t)c * 512 + kt * 128 + 2 * kk],
                       Wd2[(size_t)c * 512 + kt * 128 + 2 * kk + 1]);
    }
}

// ======================= K0: node_pre = node @ W1a^T + b1 ==================
__global__ __launch_bounds__(256)
void k0_node_pre(const float* __restrict__ node, const float* __restrict__ W1,
                 const float* __restrict__ b1) {
    extern __shared__ float sm[];
    float* sX = sm;           // 32*128
    float* sW = sm + 4096;    // 128*128  sW[k][c] = W1[c*512 + k]
    const int tid = threadIdx.x, tx = tid & 15, ty = tid >> 4;
    const int n0 = blockIdx.x * 32;

#pragma unroll
    for (int m = 0; m < 4; ++m) {
        int f4 = tid + 256 * m;
        int r = f4 >> 5, c4 = f4 & 31;
        *(float4*)(sX + r * 128 + c4 * 4) =
            *(const float4*)(node + (size_t)(n0 + r) * 128 + c4 * 4);
    }
#pragma unroll
    for (int m = 0; m < 16; ++m) {
        int idx = tid + 256 * m;
        int c = idx & 127, k4 = idx >> 7;
        float4 v = *(const float4*)(W1 + (size_t)c * 512 + k4 * 4);
        sW[(k4 * 4 + 0) * 128 + c] = v.x;
        sW[(k4 * 4 + 1) * 128 + c] = v.y;
        sW[(k4 * 4 + 2) * 128 + c] = v.z;
        sW[(k4 * 4 + 3) * 128 + c] = v.w;
    }
    __syncthreads();

    float acc[2][8] = {};
#pragma unroll
    for (int kk = 0; kk < 128; kk += 4) {
        float a[2][4];
#pragma unroll
        for (int i = 0; i < 2; ++i) {
            float4 t = *(float4*)(sX + (ty + 16 * i) * 128 + kk);
            a[i][0] = t.x; a[i][1] = t.y; a[i][2] = t.z; a[i][3] = t.w;
        }
#pragma unroll
        for (int q = 0; q < 4; ++q) {
            float4 b0 = *(float4*)(sW + (kk + q) * 128 + tx * 8);
            float4 b1v = *(float4*)(sW + (kk + q) * 128 + tx * 8 + 4);
            float bb[8] = {b0.x, b0.y, b0.z, b0.w, b1v.x, b1v.y, b1v.z, b1v.w};
#pragma unroll
            for (int i = 0; i < 2; ++i)
#pragma unroll
                for (int j = 0; j < 8; ++j) acc[i][j] += a[i][q] * bb[j];
        }
    }
#pragma unroll
    for (int i = 0; i < 2; ++i) {
        int r = n0 + ty + 16 * i;
#pragma unroll
        for (int j = 0; j < 8; ++j) {
            int c = tx * 8 + j;
            g_node_pre[(size_t)r * 128 + c] = acc[i][j] + b1[c];
        }
    }
}

// ================ K1: per-node-pair edge message kernel (bf16 MMA) =========
// R8 version (measured-best): scalar-LDS fragments, single-buffered k-tiles.
#define SA_OFF 0
#define SB_OFF 3456
#define SH_OFF 12160
#define SNP_OFF 18688
#define SAT_OFF 18944
#define SB2_OFF 19040
#define S1_WORDS 19168

__global__ __launch_bounds__(256, 2)
void k1_edges(const float* __restrict__ edge, const float* __restrict__ attn,
              const float* __restrict__ b2) {
    extern __shared__ unsigned smu[];
    unsigned* sA = smu + SA_OFF;
    unsigned* sB = smu + SB_OFF;
    unsigned* sH = smu + SH_OFF;
    float* sNP = (float*)(smu + SNP_OFF);
    float* sAt = (float*)(smu + SAT_OFF);
    float* sb2 = (float*)(smu + SB2_OFF);

    const int tid = threadIdx.x;
    const int lane = tid & 31, wid = tid >> 5;
    const int mg = wid >> 2;
    const int ng = wid & 3;
    const int g = lane >> 2, q = lane & 3;
    const int n0 = blockIdx.x * 2;
    const float* eb = edge + (size_t)n0 * (KN * EC);

    if (tid < 256) sNP[tid] = g_node_pre[(size_t)n0 * 128 + tid];
    if (tid < 96) sAt[tid] = attn[(size_t)n0 * KN + tid];
    if (tid < 128) sb2[tid] = b2[tid];

    float acc[3][4][4] = {};

    for (int kt = 0; kt < 6; ++kt) {
        __syncthreads();
#pragma unroll
        for (int m = 0; m < 6; ++m) {
            int f = tid + 256 * m;
            int row = f >> 4, c4 = f & 15;
            float4 v = *(const float4*)(eb + (size_t)row * EC + kt * 64 + c4 * 4);
            *(uint2*)(sA + row * 36 + c4 * 2) =
                make_uint2(pk(v.x, v.y), pk(v.z, v.w));
        }
#pragma unroll
        for (int m = 0; m < 4; ++m) {
            int f = tid + 256 * m;
            int kk = f >> 5, c4 = f & 31;
            *(uint4*)(sB + kk * 136 + c4 * 4) =
                *(const uint4*)(g_Wp1 + (size_t)(kt * 32 + kk) * 128 + c4 * 4);
        }
        __syncthreads();
#pragma unroll
        for (int s = 0; s < 4; ++s) {
            unsigned a[3][4], bf[4][2];
#pragma unroll
            for (int mi = 0; mi < 3; ++mi) {
                const unsigned* base = sA + (mg * 48 + mi * 16 + g) * 36 + s * 8 + q;
                a[mi][0] = base[0];
                a[mi][1] = base[8 * 36];
                a[mi][2] = base[4];
                a[mi][3] = base[8 * 36 + 4];
            }
#pragma unroll
            for (int t = 0; t < 4; ++t) {
                int n = ng * 32 + t * 8 + g;
                bf[t][0] = sB[(s * 8 + q) * 136 + n];
                bf[t][1] = sB[(s * 8 + 4 + q) * 136 + n];
            }
#pragma unroll
            for (int mi = 0; mi < 3; ++mi)
#pragma unroll
                for (int t = 0; t < 4; ++t) mma_bf16(acc[mi][t], a[mi], bf[t]);
        }
    }

#pragma unroll
    for (int mi = 0; mi < 3; ++mi) {
        int r0 = mg * 48 + mi * 16 + g;
#pragma unroll
        for (int t = 0; t < 4; ++t) {
            int c = ng * 32 + t * 8 + 2 * q;
            float np0 = sNP[mg * 128 + c], np1 = sNP[mg * 128 + c + 1];
            unsigned lo = pk(gelu_f(acc[mi][t][0] + np0), gelu_f(acc[mi][t][1] + np1));
            unsigned hi = pk(gelu_f(acc[mi][t][2] + np0), gelu_f(acc[mi][t][3] + np1));
            sH[r0 * 68 + ng * 16 + t * 4 + q] = lo;
            sH[(r0 + 8) * 68 + ng * 16 + t * 4 + q] = hi;
            acc[mi][t][0] = acc[mi][t][1] = acc[mi][t][2] = acc[mi][t][3] = 0.f;
        }
    }
    __syncthreads();

#pragma unroll
    for (int m = 0; m < 8; ++m) {
        int f = tid + 256 * m;
        int kk = f >> 5, c4 = f & 31;
        *(uint4*)(sB + kk * 136 + c4 * 4) =
            *(const uint4*)(g_Wp2 + (size_t)kk * 128 + c4 * 4);
    }
    if (tid < 2) {
        float s = 0.f;
#pragma unroll
        for (int k = 0; k < KN; ++k) s += sAt[tid * KN + k];
        g_A[n0 + tid] = s;
    }
    __syncthreads();

#pragma unroll
    for (int s = 0; s < 8; ++s) {
        unsigned a[3][4], bf[4][2];
#pragma unroll
        for (int mi = 0; mi < 3; ++mi) {
            const unsigned* base = sH + (mg * 48 + mi * 16 + g) * 68 + s * 8 + q;
            a[mi][0] = base[0];
            a[mi][1] = base[8 * 68];
            a[mi][2] = base[4];
            a[mi][3] = base[8 * 68 + 4];
        }
#pragma unroll
        for (int t = 0; t < 4; ++t) {
            int n = ng * 32 + t * 8 + g;
            bf[t][0] = sB[(s * 8 + q) * 136 + n];
            bf[t][1] = sB[(s * 8 + 4 + q) * 136 + n];
        }
#pragma unroll
        for (int mi = 0; mi < 3; ++mi)
#pragma unroll
            for (int t = 0; t < 4; ++t) mma_bf16(acc[mi][t], a[mi], bf[t]);
    }

#pragma unroll
    for (int t = 0; t < 4; ++t) {
        int c = ng * 32 + t * 8 + 2 * q;
        float bc0 = sb2[c], bc1 = sb2[c + 1];
        float p0 = 0.f, p1 = 0.f;
#pragma unroll
        for (int mi = 0; mi < 3; ++mi) {
            int r0 = mi * 16 + g;
            float w0 = sAt[mg * 48 + r0];
            float w1 = sAt[mg * 48 + r0 + 8];
            p0 += w0 * gelu_f(acc[mi][t][0] + bc0) + w1 * gelu_f(acc[mi][t][2] + bc0);
            p1 += w0 * gelu_f(acc[mi][t][1] + bc1) + w1 * gelu_f(acc[mi][t][3] + bc1);
        }
#pragma unroll
        for (int off = 16; off >= 4; off >>= 1) {
            p0 += __shfl_xor_sync(0xffffffffu, p0, off);
            p1 += __shfl_xor_sync(0xffffffffu, p1, off);
        }
        if (lane < 4) {
            int cc = ng * 32 + t * 8 + 2 * lane;
            g_S[(size_t)(n0 + mg) * 128 + cc] = p0;
            g_S[(size_t)(n0 + mg) * 128 + cc + 1] = p1;
        }
    }
}

// ============== KT: fused bf16-MMA tail, 32 nodes/block, grid 128 ==========
// phase A: x = LN1(node + (W3@S + A*b3)/30)     [MMA 32x128x128]
// phase B: H = gelu(x @ Wd1^T + bd1)            [4x MMA 32x128x128]
// phase C: out = mask * LN2(x + H @ Wd2^T + bd2)[4-kt MMA 32x128x(512)]
#define T_SB   0        // 64*136 = 8704  (weight tile bf16x2)
#define T_AB   8704     // 32*68  = 2176  (activation bf16x2: S, then x)
#define T_HB   10880    // 32*260 = 8320  (H bf16x2)
#define T_RES  19200    // 32*132 = 4224  (fp32 GEMM staging)
#define T_SX   23424    // 32*132 = 4224  (fp32 x)
#define T_RED  27648    // 1024 floats (LN partials: [0,512)=sum, [512,1024)=sumsq)
#define T_WORDS 28672

__global__ __launch_bounds__(256)
void kt_mma(const float* __restrict__ node, const float* __restrict__ b3,
            const float* __restrict__ g1, const float* __restrict__ be1,
            const float* __restrict__ bd1, const float* __restrict__ bd2,
            const float* __restrict__ g2, const float* __restrict__ be2,
            const float* __restrict__ maskp, float* __restrict__ out) {
    extern __shared__ unsigned smu[];
    unsigned* sB = smu + T_SB;
    unsigned* sAb = smu + T_AB;
    unsigned* sHb = smu + T_HB;
    float* sRes = (float*)(smu + T_RES);
    float* sX = (float*)(smu + T_SX);
    float* sRed = (float*)(smu + T_RED);   // [r*16+tx] = sum, [512 + r*16+tx] = sumsq

    const int tid = threadIdx.x;
    const int lane = tid & 31, wid = tid >> 5;
    const int mg = wid >> 2, ng = wid & 3;
    const int g = lane >> 2, q = lane & 3;
    const int tx = tid & 15, ty = tid >> 4;
    const int n0 = blockIdx.x * 32;

    // ---- fill: S (pack bf16) + W3 tile -------------------------------------
#pragma unroll
    for (int m = 0; m < 4; ++m) {
        int f = tid + 256 * m;                 // 0..1023
        int row = f >> 5, c4 = f & 31;
        float4 v = *(const float4*)(g_S + (size_t)(n0 + row) * 128 + c4 * 4);
        *(uint2*)(sAb + row * 68 + c4 * 2) = make_uint2(pk(v.x, v.y), pk(v.z, v.w));
    }
#pragma unroll
    for (int m = 0; m < 8; ++m) {
        int f = tid + 256 * m;                 // 0..2047
        int kk = f >> 5, c4 = f & 31;
        *(uint4*)(sB + kk * 136 + c4 * 4) =
            *(const uint4*)(g_Wp3 + (size_t)kk * 128 + c4 * 4);
    }
    __syncthreads();

    // ---- phase A GEMM: S @ W3^T --------------------------------------------
    float acc[4][4] = {};
    gemm32(sAb, 68, sB, mg, ng, lane, acc);
    {
        int r0 = mg * 16 + g;
#pragma unroll
        for (int t = 0; t < 4; ++t) {
            int c = ng * 32 + t * 8 + 2 * q;
            sRes[r0 * 132 + c] = acc[t][0];
            sRes[r0 * 132 + c + 1] = acc[t][1];
            sRes[(r0 + 8) * 132 + c] = acc[t][2];
            sRes[(r0 + 8) * 132 + c + 1] = acc[t][3];
        }
    }
    __syncthreads();

    // ---- phase A epilogue: LN1 ---------------------------------------------
    float xv[2][8];
#pragma unroll
    for (int i = 0; i < 2; ++i) {
        int r = ty + 16 * i, n = n0 + r;
        float As = g_A[n];
        float s = 0.f, qs = 0.f;
#pragma unroll
        for (int j = 0; j < 8; ++j) {
            int c = tx * 8 + j;
            float v = node[(size_t)n * 128 + c] +
                      (sRes[r * 132 + c] + As * b3[c]) * (1.0f / 30.0f);
            xv[i][j] = v; s += v; qs += v * v;
        }
        sRed[r * 16 + tx] = s;
        sRed[512 + r * 16 + tx] = qs;
    }
    __syncthreads();
#pragma unroll
    for (int i = 0; i < 2; ++i) {
        int r = ty + 16 * i;
        float s = 0.f, qs = 0.f;
#pragma unroll
        for (int t = 0; t < 16; ++t) {
            s += sRed[r * 16 + t];
            qs += sRed[512 + r * 16 + t];
        }
        float mu = s * (1.0f / 128.0f);
        float var = qs * (1.0f / 128.0f) - mu * mu;
        float rs = rsqrtf(var + 1e-5f);
        float o[8];
#pragma unroll
        for (int j = 0; j < 8; ++j) {
            int c = tx * 8 + j;
            o[j] = (xv[i][j] - mu) * rs * g1[c] + be1[c];
            sX[r * 132 + c] = o[j];
        }
#pragma unroll
        for (int m = 0; m < 4; ++m)
            sAb[r * 68 + tx * 4 + m] = pk(o[2 * m], o[2 * m + 1]);
    }

    // ---- phase B: H = gelu(x @ Wd1^T + bd1) --------------------------------
    for (int t = 0; t < 4; ++t) {
        __syncthreads();                        // prev MMA reads / epilogue done
#pragma unroll
        for (int m = 0; m < 8; ++m) {
            int f = tid + 256 * m;
            int kk = f >> 5, c4 = f & 31;
            *(uint4*)(sB + kk * 136 + c4 * 4) =
                *(const uint4*)(g_WpD1 + (size_t)(t * 64 + kk) * 128 + c4 * 4);
        }
        __syncthreads();
        float a2[4][4] = {};
        gemm32(sAb, 68, sB, mg, ng, lane, a2);
        int r0 = mg * 16 + g;
#pragma unroll
        for (int tp = 0; tp < 4; ++tp) {
            int cl = ng * 32 + tp * 8 + 2 * q;
            int h = t * 128 + cl;
            float bb0 = bd1[h], bb1 = bd1[h + 1];
            unsigned lo = pk(gelu_f(a2[tp][0] + bb0), gelu_f(a2[tp][1] + bb1));
            unsigned hi = pk(gelu_f(a2[tp][2] + bb0), gelu_f(a2[tp][3] + bb1));
            int widx = t * 64 + ng * 16 + tp * 4 + q;
            sHb[r0 * 260 + widx] = lo;
            sHb[(r0 + 8) * 260 + widx] = hi;
        }
    }

    // ---- phase C: acc3 = H @ Wd2^T over 4 k-tiles ---------------------------
    float acc3[4][4] = {};
    for (int kt = 0; kt < 4; ++kt) {
        __syncthreads();
#pragma unroll
        for (int m = 0; m < 8; ++m) {
            int f = tid + 256 * m;
            int kk = f >> 5, c4 = f & 31;
            *(uint4*)(sB + kk * 136 + c4 * 4) =
                *(const uint4*)(g_WpD2 + (size_t)(kt * 64 + kk) * 128 + c4 * 4);
        }
        __syncthreads();
        gemm32(sHb + kt * 64, 260, sB, mg, ng, lane, acc3);
    }
    {
        int r0 = mg * 16 + g;
#pragma unroll
        for (int t = 0; t < 4; ++t) {
            int c = ng * 32 + t * 8 + 2 * q;
            sRes[r0 * 132 + c] = acc3[t][0];
            sRes[r0 * 132 + c + 1] = acc3[t][1];
            sRes[(r0 + 8) * 132 + c] = acc3[t][2];
            sRes[(r0 + 8) * 132 + c + 1] = acc3[t][3];
        }
    }
    __syncthreads();

    // ---- phase C epilogue: LN2 + mask ---------------------------------------
    float vv[2][8];
#pragma unroll
    for (int i = 0; i < 2; ++i) {
        int r = ty + 16 * i;
        float s = 0.f, qs = 0.f;
#pragma unroll
        for (int j = 0; j < 8; ++j) {
            int c = tx * 8 + j;
            float v = sX[r * 132 + c] + sRes[r * 132 + c] + bd2[c];
            vv[i][j] = v; s += v; qs += v * v;
        }
        sRed[r * 16 + tx] = s;
        sRed[512 + r * 16 + tx] = qs;
    }
    __syncthreads();
#pragma unroll
    for (int i = 0; i < 2; ++i) {
        int r = ty + 16 * i, n = n0 + r;
        float s = 0.f, qs = 0.f;
#pragma unroll
        for (int t = 0; t < 16; ++t) {
            s += sRed[r * 16 + t];
            qs += sRed[512 + r * 16 + t];
        }
        float mu = s * (1.0f / 128.0f);
        float var = qs * (1.0f / 128.0f) - mu * mu;
        float rs = rsqrtf(var + 1e-5f);
        float mk = maskp[n];
        float o[8];
#pragma unroll
        for (int j = 0; j < 8; ++j) {
            int c = tx * 8 + j;
            o[j] = mk * ((vv[i][j] - mu) * rs * g2[c] + be2[c]);
        }
        *(float4*)(out + (size_t)n * 128 + tx * 8) = make_float4(o[0], o[1], o[2], o[3]);
        *(float4*)(out + (size_t)n * 128 + tx * 8 + 4) = make_float4(o[4], o[5], o[6], o[7]);
    }
}

// ============================== launch =====================================
extern "C" void kernel_launch(void* const* d_in, const int* in_sizes, int n_in,
                              void* d_out, int out_size) {
    const float* node = (const float*)d_in[0];
    const float* edge = (const float*)d_in[1];
    const float* mask = (const float*)d_in[2];
    const float* attn = (const float*)d_in[3];
    const float* W1   = (const float*)d_in[4];
    const float* b1   = (const float*)d_in[5];
    const float* W2   = (const float*)d_in[6];
    const float* b2   = (const float*)d_in[7];
    const float* W3   = (const float*)d_in[8];
    const float* b3   = (const float*)d_in[9];
    const float* g1   = (const float*)d_in[10];
    const float* be1  = (const float*)d_in[11];
    const float* Wd1  = (const float*)d_in[12];
    const float* bd1  = (const float*)d_in[13];
    const float* Wd2  = (const float*)d_in[14];
    const float* bd2  = (const float*)d_in[15];
    const float* g2   = (const float*)d_in[16];
    const float* be2  = (const float*)d_in[17];
    float* out = (float*)d_out;

    const size_t s0 = (size_t)(4096 + 16384) * sizeof(float);
    const size_t s1 = (size_t)S1_WORDS * sizeof(unsigned);
    const size_t st = (size_t)T_WORDS * sizeof(unsigned);

    cudaFuncSetAttribute(k0_node_pre, cudaFuncAttributeMaxDynamicSharedMemorySize, (int)s0);
    cudaFuncSetAttribute(k1_edges,    cudaFuncAttributeMaxDynamicSharedMemorySize, (int)s1);
    cudaFuncSetAttribute(kt_mma,      cudaFuncAttributeMaxDynamicSharedMemorySize, (int)st);

    k_prep<<<416, 256>>>(W1, W2, W3, Wd1, Wd2);
    k0_node_pre<<<NN / 32, 256, s0>>>(node, W1, b1);
    k1_edges<<<NN / 2, 256, s1>>>(edge, attn, b2);
    kt_mma<<<NN / 32, 256, st>>>(node, b3, g1, be1, bd1, bd2, g2, be2, mask, out);
}

// round 14
// speedup vs baseline: 2.3884x; 1.1119x over previous
#include <cuda_runtime.h>
#include <cuda_bf16.h>
#include <math.h>

#define NN 4096
#define KN 48
#define CC 128
#define EC 384
#define HD 512

// ---------------- scratch (device globals: allocation-free) ----------------
__device__ float g_node_pre[NN * CC];   // node @ W1a^T + b_m1
__device__ float g_S[NN * CC];          // sum_k attn * h2
__device__ float g_A[NN];               // sum_k attn
__device__ unsigned g_Wp1[192 * 128];   // W1b^T packed bf16x2 along k: [kk][c]
__device__ unsigned g_Wp2[64 * 128];    // W2^T  packed bf16x2 along k: [kk][c]
__device__ unsigned g_Wp3[64 * 128];    // W3    packed bf16x2: [kk][d]
__device__ unsigned g_WpD1[256 * 128];  // Wd1   packed: [t*64+kk][h_local]
__device__ unsigned g_WpD2[256 * 128];  // Wd2   packed: [kt*64+kk][c]

__device__ __forceinline__ float gelu_f(float x) {
    return 0.5f * x * (1.0f + erff(x * 0.70710678118654752440f));
}

__device__ __forceinline__ unsigned pk(float a, float b) {
    __nv_bfloat162 t = __floats2bfloat162_rn(a, b);
    return *(unsigned*)&t;
}

__device__ __forceinline__ void mma_bf16(float c[4], const unsigned a[4], const unsigned b[2]) {
    asm volatile(
        "mma.sync.aligned.m16n8k16.row.col.f32.bf16.bf16.f32 "
        "{%0,%1,%2,%3},{%4,%5,%6,%7},{%8,%9},{%0,%1,%2,%3};\n"
        : "+f"(c[0]), "+f"(c[1]), "+f"(c[2]), "+f"(c[3])
        : "r"(a[0]), "r"(a[1]), "r"(a[2]), "r"(a[3]), "r"(b[0]), "r"(b[1]));
}

#define CP_ASYNC16(dst, src) \
    asm volatile("cp.async.cg.shared.global [%0], [%1], 16;" :: "r"(dst), "l"(src))
#define CP_COMMIT() asm volatile("cp.async.commit_group;" ::)
#define CP_WAIT0()  asm volatile("cp.async.wait_group 0;" ::)

// 32xN(=128)xK(=128) block-GEMM step: A bf16x2 [32][astride], B bf16x2 [64][136]
__device__ __forceinline__ void gemm32(const unsigned* sA, int astride,
                                       const unsigned* sB, int mg, int ng,
                                       int lane, float acc[4][4]) {
    const int g = lane >> 2, q = lane & 3;
#pragma unroll
    for (int s = 0; s < 8; ++s) {
        unsigned a[4], bf[4][2];
        const unsigned* base = sA + (mg * 16 + g) * astride + s * 8 + q;
        a[0] = base[0];
        a[1] = base[8 * astride];
        a[2] = base[4];
        a[3] = base[8 * astride + 4];
#pragma unroll
        for (int t = 0; t < 4; ++t) {
            int n = ng * 32 + t * 8 + g;
            bf[t][0] = sB[(s * 8 + q) * 136 + n];
            bf[t][1] = sB[(s * 8 + 4 + q) * 136 + n];
        }
#pragma unroll
        for (int t = 0; t < 4; ++t) mma_bf16(acc[t], a, bf[t]);
    }
}

// =================== Kprep: pack ALL weights to bf16x2 =====================
__global__ __launch_bounds__(256)
void k_prep(const float* __restrict__ W1, const float* __restrict__ W2,
            const float* __restrict__ W3, const float* __restrict__ Wd1,
            const float* __restrict__ Wd2) {
    int idx = blockIdx.x * 256 + threadIdx.x;
    if (idx < 24576) {                       // g_Wp1: 192*128
        int kk = idx >> 7, c = idx & 127;
        g_Wp1[idx] = pk(W1[(size_t)c * 512 + 128 + 2 * kk],
                        W1[(size_t)c * 512 + 128 + 2 * kk + 1]);
    } else if (idx < 32768) {                // g_Wp2: 64*128
        int j = idx - 24576;
        int kk = j >> 7, c = j & 127;
        g_Wp2[j] = pk(W2[(size_t)c * 128 + 2 * kk],
                      W2[(size_t)c * 128 + 2 * kk + 1]);
    } else if (idx < 40960) {                // g_Wp3: 64*128
        int j = idx - 32768;
        int kk = j >> 7, d = j & 127;
        g_Wp3[j] = pk(W3[(size_t)d * 128 + 2 * kk],
                      W3[(size_t)d * 128 + 2 * kk + 1]);
    } else if (idx < 73728) {                // g_WpD1: 256*128
        int j = idx - 40960;
        int row = j >> 7, hh = j & 127;
        int t = row >> 6, kk = row & 63;
        g_WpD1[j] = pk(Wd1[(size_t)(t * 128 + hh) * 128 + 2 * kk],
                       Wd1[(size_t)(t * 128 + hh) * 128 + 2 * kk + 1]);
    } else if (idx < 106496) {               // g_WpD2: 256*128
        int j = idx - 73728;
        int row = j >> 7, c = j & 127;
        int kt = row >> 6, kk = row & 63;
        g_WpD2[j] = pk(Wd2[(size_t)c * 512 + kt * 128 + 2 * kk],
                       Wd2[(size_t)c * 512 + kt * 128 + 2 * kk + 1]);
    }
}

// ======================= K0: node_pre = node @ W1a^T + b1 ==================
__global__ __launch_bounds__(256)
void k0_node_pre(const float* __restrict__ node, const float* __restrict__ W1,
                 const float* __restrict__ b1) {
    extern __shared__ float sm[];
    float* sX = sm;           // 32*128
    float* sW = sm + 4096;    // 128*128  sW[k][c] = W1[c*512 + k]
    const int tid = threadIdx.x, tx = tid & 15, ty = tid >> 4;
    const int n0 = blockIdx.x * 32;

#pragma unroll
    for (int m = 0; m < 4; ++m) {
        int f4 = tid + 256 * m;
        int r = f4 >> 5, c4 = f4 & 31;
        *(float4*)(sX + r * 128 + c4 * 4) =
            *(const float4*)(node + (size_t)(n0 + r) * 128 + c4 * 4);
    }
#pragma unroll
    for (int m = 0; m < 16; ++m) {
        int idx = tid + 256 * m;
        int c = idx & 127, k4 = idx >> 7;
        float4 v = *(const float4*)(W1 + (size_t)c * 512 + k4 * 4);
        sW[(k4 * 4 + 0) * 128 + c] = v.x;
        sW[(k4 * 4 + 1) * 128 + c] = v.y;
        sW[(k4 * 4 + 2) * 128 + c] = v.z;
        sW[(k4 * 4 + 3) * 128 + c] = v.w;
    }
    __syncthreads();

    float acc[2][8] = {};
#pragma unroll
    for (int kk = 0; kk < 128; kk += 4) {
        float a[2][4];
#pragma unroll
        for (int i = 0; i < 2; ++i) {
            float4 t = *(float4*)(sX + (ty + 16 * i) * 128 + kk);
            a[i][0] = t.x; a[i][1] = t.y; a[i][2] = t.z; a[i][3] = t.w;
        }
#pragma unroll
        for (int q = 0; q < 4; ++q) {
            float4 b0 = *(float4*)(sW + (kk + q) * 128 + tx * 8);
            float4 b1v = *(float4*)(sW + (kk + q) * 128 + tx * 8 + 4);
            float bb[8] = {b0.x, b0.y, b0.z, b0.w, b1v.x, b1v.y, b1v.z, b1v.w};
#pragma unroll
            for (int i = 0; i < 2; ++i)
#pragma unroll
                for (int j = 0; j < 8; ++j) acc[i][j] += a[i][q] * bb[j];
        }
    }
#pragma unroll
    for (int i = 0; i < 2; ++i) {
        int r = n0 + ty + 16 * i;
#pragma unroll
        for (int j = 0; j < 8; ++j) {
            int c = tx * 8 + j;
            g_node_pre[(size_t)r * 128 + c] = acc[i][j] + b1[c];
        }
    }
}

// ================ K1: per-node-pair edge message kernel (bf16 MMA) =========
// R8 fragment pattern (scalar LDS, k-major B) + double-buffered k-tiles:
// A staged in registers (LDG overlaps MMA), B via cp.async. W2 split into
// 2 half-tiles prefetched into freed B buffers (fill fully hidden).
#define A0_OFF 0            // 96*36
#define B0_OFF 3456         // 32*136
#define A1_OFF 7808         // 96*36
#define B1_OFF 11264        // 32*136
#define SH1_OFF 15616       // 96*68
#define NP_OFF 22144        // 256 f
#define AT_OFF 22400        // 96 f (pad to 128)
#define B2A_OFF 22528       // 128 f
#define S1_WORDS 22656

__global__ __launch_bounds__(256, 2)
void k1_edges(const float* __restrict__ edge, const float* __restrict__ attn,
              const float* __restrict__ b2) {
    extern __shared__ unsigned smu[];
    unsigned* sH = smu + SH1_OFF;
    float* sNP = (float*)(smu + NP_OFF);
    float* sAt = (float*)(smu + AT_OFF);
    float* sb2 = (float*)(smu + B2A_OFF);
    const unsigned smem_base = (unsigned)__cvta_generic_to_shared(smu);

    const int tid = threadIdx.x;
    const int lane = tid & 31, wid = tid >> 5;
    const int mg = wid >> 2;
    const int ng = wid & 3;
    const int g = lane >> 2, q = lane & 3;
    const int n0 = blockIdx.x * 2;
    const float* eb = edge + (size_t)n0 * (KN * EC);

    sNP[tid] = g_node_pre[(size_t)n0 * 128 + tid];
    if (tid < 96) sAt[tid] = attn[(size_t)n0 * KN + tid];
    if (tid < 128) sb2[tid] = b2[tid];

    // ---- prologue: tile 0 ----
#pragma unroll
    for (int m = 0; m < 6; ++m) {
        int f = tid + 256 * m;
        int row = f >> 4, c4 = f & 15;
        float4 v = *(const float4*)(eb + (size_t)row * EC + c4 * 4);
        *(uint2*)(smu + A0_OFF + row * 36 + c4 * 2) =
            make_uint2(pk(v.x, v.y), pk(v.z, v.w));
    }
#pragma unroll
    for (int m = 0; m < 4; ++m) {
        int f = tid + 256 * m;
        int row = f >> 5, j = f & 31;
        CP_ASYNC16(smem_base + (B0_OFF + row * 136 + j * 4) * 4,
                   g_Wp1 + (size_t)row * 128 + j * 4);
    }
    CP_COMMIT();
    CP_WAIT0();
    __syncthreads();

    float acc[3][4][4] = {};
    float4 st[6];

    // ---------------- GEMM1b: 6 double-buffered k-tiles of 64 --------------
    for (int kt = 0; kt < 6; ++kt) {
        const unsigned* sA = smu + ((kt & 1) ? A1_OFF : A0_OFF);
        const unsigned* sB = smu + ((kt & 1) ? B1_OFF : B0_OFF);
        if (kt < 5) {
#pragma unroll
            for (int m = 0; m < 6; ++m) {
                int f = tid + 256 * m;
                int row = f >> 4, c4 = f & 15;
                st[m] = *(const float4*)(eb + (size_t)row * EC + (kt + 1) * 64 + c4 * 4);
            }
            unsigned bdst = smem_base + (((kt + 1) & 1) ? B1_OFF : B0_OFF) * 4;
#pragma unroll
            for (int m = 0; m < 4; ++m) {
                int f = tid + 256 * m;
                int row = f >> 5, j = f & 31;
                CP_ASYNC16(bdst + (row * 136 + j * 4) * 4,
                           g_Wp1 + (size_t)((kt + 1) * 32 + row) * 128 + j * 4);
            }
            CP_COMMIT();
        } else {
            // prefetch W2 half-tile 0 (kk 0..31) into B0 (free since kt=4)
#pragma unroll
            for (int m = 0; m < 4; ++m) {
                int f = tid + 256 * m;
                int row = f >> 5, j = f & 31;
                CP_ASYNC16(smem_base + (B0_OFF + row * 136 + j * 4) * 4,
                           g_Wp2 + (size_t)row * 128 + j * 4);
            }
            CP_COMMIT();
        }
#pragma unroll
        for (int s = 0; s < 4; ++s) {
            unsigned a[3][4], bf[4][2];
#pragma unroll
            for (int mi = 0; mi < 3; ++mi) {
                const unsigned* base = sA + (mg * 48 + mi * 16 + g) * 36 + s * 8 + q;
                a[mi][0] = base[0];
                a[mi][1] = base[8 * 36];
                a[mi][2] = base[4];
                a[mi][3] = base[8 * 36 + 4];
            }
#pragma unroll
            for (int t = 0; t < 4; ++t) {
                int n = ng * 32 + t * 8 + g;
                bf[t][0] = sB[(s * 8 + q) * 136 + n];
                bf[t][1] = sB[(s * 8 + 4 + q) * 136 + n];
            }
#pragma unroll
            for (int mi = 0; mi < 3; ++mi)
#pragma unroll
                for (int t = 0; t < 4; ++t) mma_bf16(acc[mi][t], a[mi], bf[t]);
        }
        if (kt < 5) {
            unsigned* dA = smu + (((kt + 1) & 1) ? A1_OFF : A0_OFF);
#pragma unroll
            for (int m = 0; m < 6; ++m) {
                int f = tid + 256 * m;
                int row = f >> 4, c4 = f & 15;
                *(uint2*)(dA + row * 36 + c4 * 2) =
                    make_uint2(pk(st[m].x, st[m].y), pk(st[m].z, st[m].w));
            }
            CP_WAIT0();
        }
        __syncthreads();
    }

    // ---- epilogue 1: kick W2 half-tile 1 -> B1; h1 = gelu(node_pre+acc) ----
#pragma unroll
    for (int m = 0; m < 4; ++m) {
        int f = tid + 256 * m;
        int row = f >> 5, j = f & 31;
        CP_ASYNC16(smem_base + (B1_OFF + row * 136 + j * 4) * 4,
                   g_Wp2 + (size_t)(32 + row) * 128 + j * 4);
    }
    CP_COMMIT();
#pragma unroll
    for (int mi = 0; mi < 3; ++mi) {
        int r0 = mg * 48 + mi * 16 + g;
#pragma unroll
        for (int t = 0; t < 4; ++t) {
            int c = ng * 32 + t * 8 + 2 * q;
            float np0 = sNP[mg * 128 + c], np1 = sNP[mg * 128 + c + 1];
            unsigned lo = pk(gelu_f(acc[mi][t][0] + np0), gelu_f(acc[mi][t][1] + np1));
            unsigned hi = pk(gelu_f(acc[mi][t][2] + np0), gelu_f(acc[mi][t][3] + np1));
            sH[r0 * 68 + ng * 16 + t * 4 + q] = lo;
            sH[(r0 + 8) * 68 + ng * 16 + t * 4 + q] = hi;
            acc[mi][t][0] = acc[mi][t][1] = acc[mi][t][2] = acc[mi][t][3] = 0.f;
        }
    }
    if (tid < 2) {
        float s = 0.f;
#pragma unroll
        for (int k = 0; k < KN; ++k) s += sAt[tid * KN + k];
        g_A[n0 + tid] = s;
    }
    CP_WAIT0();
    __syncthreads();

    // ---------------- GEMM2: h1 @ W2^T (8 k16 steps, B0 then B1) -----------
    const unsigned* sB0p = smu + B0_OFF;
    const unsigned* sB1p = smu + B1_OFF;
#pragma unroll
    for (int s = 0; s < 8; ++s) {
        const unsigned* sBp = (s < 4) ? sB0p : sB1p;
        int ss = s & 3;
        unsigned a[3][4], bf[4][2];
#pragma unroll
        for (int mi = 0; mi < 3; ++mi) {
            const unsigned* base = sH + (mg * 48 + mi * 16 + g) * 68 + s * 8 + q;
            a[mi][0] = base[0];
            a[mi][1] = base[8 * 68];
            a[mi][2] = base[4];
            a[mi][3] = base[8 * 68 + 4];
        }
#pragma unroll
        for (int t = 0; t < 4; ++t) {
            int n = ng * 32 + t * 8 + g;
            bf[t][0] = sBp[(ss * 8 + q) * 136 + n];
            bf[t][1] = sBp[(ss * 8 + 4 + q) * 136 + n];
        }
#pragma unroll
        for (int mi = 0; mi < 3; ++mi)
#pragma unroll
            for (int t = 0; t < 4; ++t) mma_bf16(acc[mi][t], a[mi], bf[t]);
    }

    // ---- epilogue 2: gelu(+b2), attn-weighted reduce over the 48 rows -----
#pragma unroll
    for (int t = 0; t < 4; ++t) {
        int c = ng * 32 + t * 8 + 2 * q;
        float bc0 = sb2[c], bc1 = sb2[c + 1];
        float p0 = 0.f, p1 = 0.f;
#pragma unroll
        for (int mi = 0; mi < 3; ++mi) {
            int r0 = mi * 16 + g;
            float w0 = sAt[mg * 48 + r0];
            float w1 = sAt[mg * 48 + r0 + 8];
            p0 += w0 * gelu_f(acc[mi][t][0] + bc0) + w1 * gelu_f(acc[mi][t][2] + bc0);
            p1 += w0 * gelu_f(acc[mi][t][1] + bc1) + w1 * gelu_f(acc[mi][t][3] + bc1);
        }
#pragma unroll
        for (int off = 16; off >= 4; off >>= 1) {
            p0 += __shfl_xor_sync(0xffffffffu, p0, off);
            p1 += __shfl_xor_sync(0xffffffffu, p1, off);
        }
        if (lane < 4) {
            int cc = ng * 32 + t * 8 + 2 * lane;
            g_S[(size_t)(n0 + mg) * 128 + cc] = p0;
            g_S[(size_t)(n0 + mg) * 128 + cc + 1] = p1;
        }
    }
}

// ============== KT: fused bf16-MMA tail, 32 nodes/block, grid 128 ==========
#define T_SB   0
#define T_AB   8704
#define T_HB   10880
#define T_RES  19200
#define T_SX   23424
#define T_RED  27648
#define T_WORDS 28672

__global__ __launch_bounds__(256)
void kt_mma(const float* __restrict__ node, const float* __restrict__ b3,
            const float* __restrict__ g1, const float* __restrict__ be1,
            const float* __restrict__ bd1, const float* __restrict__ bd2,
            const float* __restrict__ g2, const float* __restrict__ be2,
            const float* __restrict__ maskp, float* __restrict__ out) {
    extern __shared__ unsigned smu[];
    unsigned* sB = smu + T_SB;
    unsigned* sAb = smu + T_AB;
    unsigned* sHb = smu + T_HB;
    float* sRes = (float*)(smu + T_RES);
    float* sX = (float*)(smu + T_SX);
    float* sRed = (float*)(smu + T_RED);

    const int tid = threadIdx.x;
    const int lane = tid & 31, wid = tid >> 5;
    const int mg = wid >> 2, ng = wid & 3;
    const int g = lane >> 2, q = lane & 3;
    const int tx = tid & 15, ty = tid >> 4;
    const int n0 = blockIdx.x * 32;

#pragma unroll
    for (int m = 0; m < 4; ++m) {
        int f = tid + 256 * m;
        int row = f >> 5, c4 = f & 31;
        float4 v = *(const float4*)(g_S + (size_t)(n0 + row) * 128 + c4 * 4);
        *(uint2*)(sAb + row * 68 + c4 * 2) = make_uint2(pk(v.x, v.y), pk(v.z, v.w));
    }
#pragma unroll
    for (int m = 0; m < 8; ++m) {
        int f = tid + 256 * m;
        int kk = f >> 5, c4 = f & 31;
        *(uint4*)(sB + kk * 136 + c4 * 4) =
            *(const uint4*)(g_Wp3 + (size_t)kk * 128 + c4 * 4);
    }
    __syncthreads();

    float acc[4][4] = {};
    gemm32(sAb, 68, sB, mg, ng, lane, acc);
    {
        int r0 = mg * 16 + g;
#pragma unroll
        for (int t = 0; t < 4; ++t) {
            int c = ng * 32 + t * 8 + 2 * q;
            sRes[r0 * 132 + c] = acc[t][0];
            sRes[r0 * 132 + c + 1] = acc[t][1];
            sRes[(r0 + 8) * 132 + c] = acc[t][2];
            sRes[(r0 + 8) * 132 + c + 1] = acc[t][3];
        }
    }
    __syncthreads();

    float xv[2][8];
#pragma unroll
    for (int i = 0; i < 2; ++i) {
        int r = ty + 16 * i, n = n0 + r;
        float As = g_A[n];
        float s = 0.f, qs = 0.f;
#pragma unroll
        for (int j = 0; j < 8; ++j) {
            int c = tx * 8 + j;
            float v = node[(size_t)n * 128 + c] +
                      (sRes[r * 132 + c] + As * b3[c]) * (1.0f / 30.0f);
            xv[i][j] = v; s += v; qs += v * v;
        }
        sRed[r * 16 + tx] = s;
        sRed[512 + r * 16 + tx] = qs;
    }
    __syncthreads();
#pragma unroll
    for (int i = 0; i < 2; ++i) {
        int r = ty + 16 * i;
        float s = 0.f, qs = 0.f;
#pragma unroll
        for (int t = 0; t < 16; ++t) {
            s += sRed[r * 16 + t];
            qs += sRed[512 + r * 16 + t];
        }
        float mu = s * (1.0f / 128.0f);
        float var = qs * (1.0f / 128.0f) - mu * mu;
        float rs = rsqrtf(var + 1e-5f);
        float o[8];
#pragma unroll
        for (int j = 0; j < 8; ++j) {
            int c = tx * 8 + j;
            o[j] = (xv[i][j] - mu) * rs * g1[c] + be1[c];
            sX[r * 132 + c] = o[j];
        }
#pragma unroll
        for (int m = 0; m < 4; ++m)
            sAb[r * 68 + tx * 4 + m] = pk(o[2 * m], o[2 * m + 1]);
    }

    for (int t = 0; t < 4; ++t) {
        __syncthreads();
#pragma unroll
        for (int m = 0; m < 8; ++m) {
            int f = tid + 256 * m;
            int kk = f >> 5, c4 = f & 31;
            *(uint4*)(sB + kk * 136 + c4 * 4) =
                *(const uint4*)(g_WpD1 + (size_t)(t * 64 + kk) * 128 + c4 * 4);
        }
        __syncthreads();
        float a2[4][4] = {};
        gemm32(sAb, 68, sB, mg, ng, lane, a2);
        int r0 = mg * 16 + g;
#pragma unroll
        for (int tp = 0; tp < 4; ++tp) {
            int cl = ng * 32 + tp * 8 + 2 * q;
            int h = t * 128 + cl;
            float bb0 = bd1[h], bb1 = bd1[h + 1];
            unsigned lo = pk(gelu_f(a2[tp][0] + bb0), gelu_f(a2[tp][1] + bb1));
            unsigned hi = pk(gelu_f(a2[tp][2] + bb0), gelu_f(a2[tp][3] + bb1));
            int widx = t * 64 + ng * 16 + tp * 4 + q;
            sHb[r0 * 260 + widx] = lo;
            sHb[(r0 + 8) * 260 + widx] = hi;
        }
    }

    float acc3[4][4] = {};
    for (int kt = 0; kt < 4; ++kt) {
        __syncthreads();
#pragma unroll
        for (int m = 0; m < 8; ++m) {
            int f = tid + 256 * m;
            int kk = f >> 5, c4 = f & 31;
            *(uint4*)(sB + kk * 136 + c4 * 4) =
                *(const uint4*)(g_WpD2 + (size_t)(kt * 64 + kk) * 128 + c4 * 4);
        }
        __syncthreads();
        gemm32(sHb + kt * 64, 260, sB, mg, ng, lane, acc3);
    }
    {
        int r0 = mg * 16 + g;
#pragma unroll
        for (int t = 0; t < 4; ++t) {
            int c = ng * 32 + t * 8 + 2 * q;
            sRes[r0 * 132 + c] = acc3[t][0];
            sRes[r0 * 132 + c + 1] = acc3[t][1];
            sRes[(r0 + 8) * 132 + c] = acc3[t][2];
            sRes[(r0 + 8) * 132 + c + 1] = acc3[t][3];
        }
    }
    __syncthreads();

    float vv[2][8];
#pragma unroll
    for (int i = 0; i < 2; ++i) {
        int r = ty + 16 * i;
        float s = 0.f, qs = 0.f;
#pragma unroll
        for (int j = 0; j < 8; ++j) {
            int c = tx * 8 + j;
            float v = sX[r * 132 + c] + sRes[r * 132 + c] + bd2[c];
            vv[i][j] = v; s += v; qs += v * v;
        }
        sRed[r * 16 + tx] = s;
        sRed[512 + r * 16 + tx] = qs;
    }
    __syncthreads();
#pragma unroll
    for (int i = 0; i < 2; ++i) {
        int r = ty + 16 * i, n = n0 + r;
        float s = 0.f, qs = 0.f;
#pragma unroll
        for (int t = 0; t < 16; ++t) {
            s += sRed[r * 16 + t];
            qs += sRed[512 + r * 16 + t];
        }
        float mu = s * (1.0f / 128.0f);
        float var = qs * (1.0f / 128.0f) - mu * mu;
        float rs = rsqrtf(var + 1e-5f);
        float mk = maskp[n];
        float o[8];
#pragma unroll
        for (int j = 0; j < 8; ++j) {
            int c = tx * 8 + j;
            o[j] = mk * ((vv[i][j] - mu) * rs * g2[c] + be2[c]);
        }
        *(float4*)(out + (size_t)n * 128 + tx * 8) = make_float4(o[0], o[1], o[2], o[3]);
        *(float4*)(out + (size_t)n * 128 + tx * 8 + 4) = make_float4(o[4], o[5], o[6], o[7]);
    }
}

// ============================== launch =====================================
extern "C" void kernel_launch(void* const* d_in, const int* in_sizes, int n_in,
                              void* d_out, int out_size) {
    const float* node = (const float*)d_in[0];
    const float* edge = (const float*)d_in[1];
    const float* mask = (const float*)d_in[2];
    const float* attn = (const float*)d_in[3];
    const float* W1   = (const float*)d_in[4];
    const float* b1   = (const float*)d_in[5];
    const float* W2   = (const float*)d_in[6];
    const float* b2   = (const float*)d_in[7];
    const float* W3   = (const float*)d_in[8];
    const float* b3   = (const float*)d_in[9];
    const float* g1   = (const float*)d_in[10];
    const float* be1  = (const float*)d_in[11];
    const float* Wd1  = (const float*)d_in[12];
    const float* bd1  = (const float*)d_in[13];
    const float* Wd2  = (const float*)d_in[14];
    const float* bd2  = (const float*)d_in[15];
    const float* g2   = (const float*)d_in[16];
    const float* be2  = (const float*)d_in[17];
    float* out = (float*)d_out;

    const size_t s0 = (size_t)(4096 + 16384) * sizeof(float);
    const size_t s1 = (size_t)S1_WORDS * sizeof(unsigned);
    const size_t st = (size_t)T_WORDS * sizeof(unsigned);

    cudaFuncSetAttribute(k0_node_pre, cudaFuncAttributeMaxDynamicSharedMemorySize, (int)s0);
    cudaFuncSetAttribute(k1_edges,    cudaFuncAttributeMaxDynamicSharedMemorySize, (int)s1);
    cudaFuncSetAttribute(kt_mma,      cudaFuncAttributeMaxDynamicSharedMemorySize, (int)st);

    k_prep<<<416, 256>>>(W1, W2, W3, Wd1, Wd2);
    k0_node_pre<<<NN / 32, 256, s0>>>(node, W1, b1);
    k1_edges<<<NN / 2, 256, s1>>>(edge, attn, b2);
    kt_mma<<<NN / 32, 256, st>>>(node, b3, g1, be1, bd1, bd2, g2, be2, mask, out);
}